// round 4
// baseline (speedup 1.0000x reference)
#include <cuda_runtime.h>
#include <cstdint>

// ---------------- problem constants (fixed by the dataset) ----------------
#define NB    240
#define NS    64
#define NHID  768
#define NH    12
#define HD    64
#define L0    384
#define L1    128
#define LTOT  576
#define NCHUNK 9

// device-global scratch (allocation-free)
__device__ float g_q  [(size_t)NB * NH * NS * HD];        // q, tf32-rounded
__device__ float g_hid[(size_t)NB * NS * NHID];           // hidden, tf32-rounded
__device__ float g_w  [(size_t)3 * NHID * NHID];          // Wq|Wk|Wv, tf32-rounded

// ---------------- tf32 helpers ----------------
__device__ __forceinline__ uint32_t f2tf(float x) {
    uint32_t r;
    asm("cvt.rna.tf32.f32 %0, %1;" : "=r"(r) : "f"(x));
    return r;
}
__device__ __forceinline__ float f2tf_f(float x) { return __uint_as_float(f2tf(x)); }
__device__ __forceinline__ uint32_t fu(float x) { return __float_as_uint(x); }

#define MMA_TF32(c, a, b0, b1)                                              \
    asm volatile(                                                           \
        "mma.sync.aligned.m16n8k8.row.col.f32.tf32.tf32.f32 "               \
        "{%0,%1,%2,%3}, {%4,%5,%6,%7}, {%8,%9}, {%0,%1,%2,%3};\n"           \
        : "+f"((c)[0]), "+f"((c)[1]), "+f"((c)[2]), "+f"((c)[3])            \
        : "r"((a)[0]), "r"((a)[1]), "r"((a)[2]), "r"((a)[3]),               \
          "r"(b0), "r"(b1))

__device__ __forceinline__ void cp16(float* dst, const float* src) {
    uint32_t d = (uint32_t)__cvta_generic_to_shared(dst);
    asm volatile("cp.async.cg.shared.global [%0], [%1], 16;\n"
                 :: "r"(d), "l"(src));
}
__device__ __forceinline__ void cp_commit() {
    asm volatile("cp.async.commit_group;\n");
}
template <int N> __device__ __forceinline__ void cp_wait() {
    asm volatile("cp.async.wait_group %0;\n" :: "n"(N));
}

// =====================================================================
// Elementwise tf32 rounding (RNA) src -> dst, float4-vectorized.
// =====================================================================
__global__ __launch_bounds__(256) void round_tf32_kernel(
    const float4* __restrict__ src, float4* __restrict__ dst, int n4)
{
    int i = blockIdx.x * blockDim.x + threadIdx.x;
    const int stride = gridDim.x * blockDim.x;
    for (; i < n4; i += stride) {
        float4 v = src[i];
        v.x = f2tf_f(v.x); v.y = f2tf_f(v.y);
        v.z = f2tf_f(v.z); v.w = f2tf_f(v.w);
        dst[i] = v;
    }
}

// =====================================================================
// QKV projection, tf32 mma, 3-stage cp.async pipeline.
// Inputs (g_hid, g_w) are pre-rounded tf32 -> raw-bit fragment loads.
// Block tile 128x64, BK=32, 256 thr = 8 warps (4x2), warp tile 32x32.
// smem stage: A[128][36] + B[64][36]; 3 stages = 82944 B.
// =====================================================================
#define GLD   36
#define A_SZ  (128 * GLD)
#define B_SZ  (64 * GLD)
#define STAGE (A_SZ + B_SZ)

__global__ __launch_bounds__(256, 2) void qkv_gemm_tc2(
    const float* __restrict__ bq, const float* __restrict__ bk_,
    const float* __restrict__ bv,
    float* __restrict__ out_k, float* __restrict__ out_v)
{
    extern __shared__ float smg[];

    const int m0  = blockIdx.x * 128;
    const int n0g = blockIdx.y * 64;
    const int mat = n0g / NHID;
    const int n0  = n0g - mat * NHID;

    const float* Ag = g_hid;
    const float* Bg = g_w + (size_t)mat * NHID * NHID;
    const float* bi = (mat == 0) ? bq : (mat == 1) ? bk_ : bv;

    const int tid  = threadIdx.x;
    const int lane = tid & 31;
    const int w    = tid >> 5;
    const int wm   = w & 3;
    const int wn   = w >> 2;
    const int lq   = lane & 3;
    const int lr   = lane >> 2;

    // async-load mapping
    const int arow = tid >> 1;            // 0..127
    const int acb  = (tid & 1) * 16;      // 0 / 16
    const int brow = tid >> 2;            // 0..63
    const int bcb  = (tid & 3) * 8;       // 0,8,16,24

    auto load_stage = [&](int s, int k0) {
        float* A = smg + s * STAGE;
        float* B = A + A_SZ;
        const float* ag = Ag + (size_t)(m0 + arow) * NHID + k0 + acb;
        const float* bg = Bg + (size_t)(n0 + brow) * NHID + k0 + bcb;
        float* ad = A + arow * GLD + acb;
        float* bd = B + brow * GLD + bcb;
        cp16(ad + 0,  ag + 0);
        cp16(ad + 4,  ag + 4);
        cp16(ad + 8,  ag + 8);
        cp16(ad + 12, ag + 12);
        cp16(bd + 0,  bg + 0);
        cp16(bd + 4,  bg + 4);
    };

    float acc[2][4][4];
#pragma unroll
    for (int mt = 0; mt < 2; mt++)
#pragma unroll
        for (int nt = 0; nt < 4; nt++)
#pragma unroll
            for (int i = 0; i < 4; i++) acc[mt][nt][i] = 0.f;

    auto compute = [&](int s) {
        const float* A = smg + s * STAGE;
        const float* B = A + A_SZ;
#pragma unroll
        for (int ks = 0; ks < 4; ks++) {
            const int kb = ks * 8;
            uint32_t af[2][4];
#pragma unroll
            for (int mt = 0; mt < 2; mt++) {
                const int r = wm * 32 + mt * 16 + lr;
                af[mt][0] = fu(A[r * GLD + kb + lq]);
                af[mt][1] = fu(A[(r + 8) * GLD + kb + lq]);
                af[mt][2] = fu(A[r * GLD + kb + 4 + lq]);
                af[mt][3] = fu(A[(r + 8) * GLD + kb + 4 + lq]);
            }
            uint32_t bf[4][2];
#pragma unroll
            for (int nt = 0; nt < 4; nt++) {
                const int n = wn * 32 + nt * 8 + lr;
                bf[nt][0] = fu(B[n * GLD + kb + lq]);
                bf[nt][1] = fu(B[n * GLD + kb + 4 + lq]);
            }
#pragma unroll
            for (int mt = 0; mt < 2; mt++)
#pragma unroll
                for (int nt = 0; nt < 4; nt++)
                    MMA_TF32(acc[mt][nt], af[mt], bf[nt][0], bf[nt][1]);
        }
    };

    // prologue: 2 stages in flight
    load_stage(0, 0);  cp_commit();
    load_stage(1, 32); cp_commit();

    for (int it = 0; it < 24; it++) {
        cp_wait<1>();
        __syncthreads();
        if (it + 2 < 24) load_stage((it + 2) % 3, (it + 2) * 32);
        cp_commit();                 // empty group ok for tail: keeps accounting
        compute(it % 3);
    }

    // epilogue: bias + scatter to [b, h, s, d]; q rounded to tf32
    float* dst = (mat == 0) ? g_q : (mat == 1) ? out_k : out_v;
#pragma unroll
    for (int nt = 0; nt < 4; nt++) {
        const int ncol = n0 + wn * 32 + nt * 8 + 2 * lq;
        const float b0 = bi[ncol];
        const float b1 = bi[ncol + 1];
        const int h = ncol >> 6;
        const int d = ncol & 63;
#pragma unroll
        for (int mt = 0; mt < 2; mt++) {
            const int r = wm * 32 + mt * 16 + lr;
#pragma unroll
            for (int half = 0; half < 2; half++) {
                const int m = m0 + r + 8 * half;
                const int b = m >> 6;
                const int s = m & 63;
                const size_t idx = (((size_t)b * NH + h) * NS + s) * HD + d;
                float2 v;
                v.x = acc[mt][nt][2 * half + 0] + b0;
                v.y = acc[mt][nt][2 * half + 1] + b1;
                if (mat == 0) { v.x = f2tf_f(v.x); v.y = f2tf_f(v.y); }
                *(float2*)&dst[idx] = v;
            }
        }
    }
}

// =====================================================================
// Flash cache attention, tf32 mma (round-3 structure; q pre-rounded).
// =====================================================================
#define KV_LD 68
#define KV_TILE (64 * KV_LD)

__global__ __launch_bounds__(128, 3) void attn_flash(
    const float* __restrict__ mask,
    const float* __restrict__ c0k, const float* __restrict__ c0v,
    const float* __restrict__ c1k, const float* __restrict__ c1v,
    const float* __restrict__ kself, const float* __restrict__ vself,
    float* __restrict__ outctx)
{
    extern __shared__ float sm[];
    float* kbuf   = sm;                       // [2][64][68]
    float* vbuf   = kbuf + 2 * KV_TILE;       // [2][64][68]
    float* mask_s = vbuf + 2 * KV_TILE;       // [576]

    const int bh   = blockIdx.x;
    const int b    = bh / NH;
    const int h    = bh - b * NH;
    const int tid  = threadIdx.x;
    const int lane = tid & 31;
    const int w    = tid >> 5;
    const int lq   = lane & 3;
    const int lr   = lane >> 2;
    const int qb   = lane & 28;

    const float* c0kb = c0k + ((size_t)(b & 7) * NH + h) * L0 * HD;
    const float* c0vb = c0v + ((size_t)(b & 7) * NH + h) * L0 * HD;
    const float* c1kb = c1k + (size_t)bh * L1 * HD;
    const float* c1vb = c1v + (size_t)bh * L1 * HD;
    const float* ksb  = kself + (size_t)bh * NS * HD;
    const float* vsb  = vself + (size_t)bh * NS * HD;

    auto ksrc_of = [&](int c) -> const float* {
        return (c < 6) ? (c0kb + c * 64 * HD)
             : (c < 8) ? (c1kb + (c - 6) * 64 * HD) : ksb;
    };
    auto vsrc_of = [&](int c) -> const float* {
        return (c < 6) ? (c0vb + c * 64 * HD)
             : (c < 8) ? (c1vb + (c - 6) * 64 * HD) : vsb;
    };

    auto load_tile = [&](float* buf, const float* src) {
        const int r  = tid >> 1;
        const int c0 = (tid & 1) * 32;
        float* d = buf + r * KV_LD + c0;
        const float* s = src + r * HD + c0;
#pragma unroll
        for (int i = 0; i < 8; i++) cp16(d + 4 * i, s + 4 * i);
    };

    // prologue: Q -> kbuf[1]; chunk0 -> buf0; mask
    load_tile(kbuf + KV_TILE, g_q + (size_t)bh * NS * HD);
    cp_commit();
    load_tile(kbuf, ksrc_of(0));
    load_tile(vbuf, vsrc_of(0));
    cp_commit();

    for (int i = tid; i < LTOT; i += 128)
        mask_s[i] = mask[(size_t)b * LTOT + i];

    cp_wait<1>();
    __syncthreads();

    // Q fragments (g_q already tf32-rounded -> raw bits)
    uint32_t qa[8][4];
    {
        const float* qs = kbuf + KV_TILE;
        const int r = w * 16 + lr;
#pragma unroll
        for (int ks = 0; ks < 8; ks++) {
            qa[ks][0] = fu(qs[r * KV_LD + ks * 8 + lq]);
            qa[ks][1] = fu(qs[(r + 8) * KV_LD + ks * 8 + lq]);
            qa[ks][2] = fu(qs[r * KV_LD + ks * 8 + 4 + lq]);
            qa[ks][3] = fu(qs[(r + 8) * KV_LD + ks * 8 + 4 + lq]);
        }
    }
    __syncthreads();

    float m0 = -1e30f, m1 = -1e30f;
    float l0 = 0.f,    l1 = 0.f;
    float o[8][4];
#pragma unroll
    for (int dt = 0; dt < 8; dt++)
#pragma unroll
        for (int i = 0; i < 4; i++) o[dt][i] = 0.f;

    for (int c = 0; c < NCHUNK; c++) {
        if (c < NCHUNK - 1) {
            float* kb = kbuf + ((c + 1) & 1) * KV_TILE;
            float* vb = vbuf + ((c + 1) & 1) * KV_TILE;
            load_tile(kb, ksrc_of(c + 1));
            load_tile(vb, vsrc_of(c + 1));
            cp_commit();
            cp_wait<1>();
        } else {
            cp_wait<0>();
        }
        __syncthreads();

        const float* K = kbuf + (c & 1) * KV_TILE;
        const float* V = vbuf + (c & 1) * KV_TILE;

        float cS[8][4];
#pragma unroll
        for (int nt = 0; nt < 8; nt++)
#pragma unroll
            for (int i = 0; i < 4; i++) cS[nt][i] = 0.f;

#pragma unroll
        for (int ks = 0; ks < 8; ks++) {
#pragma unroll
            for (int nt = 0; nt < 8; nt++) {
                const int n = nt * 8 + lr;
                uint32_t b0 = f2tf(K[n * KV_LD + ks * 8 + lq]);
                uint32_t b1 = f2tf(K[n * KV_LD + ks * 8 + 4 + lq]);
                MMA_TF32(cS[nt], qa[ks], b0, b1);
            }
        }

        float cm0 = -1e30f, cm1 = -1e30f;
#pragma unroll
        for (int nt = 0; nt < 8; nt++) {
            const int col = c * 64 + nt * 8 + 2 * lq;
            const float mv0 = mask_s[col];
            const float mv1 = mask_s[col + 1];
            cS[nt][0] = cS[nt][0] * 0.125f + mv0;
            cS[nt][1] = cS[nt][1] * 0.125f + mv1;
            cS[nt][2] = cS[nt][2] * 0.125f + mv0;
            cS[nt][3] = cS[nt][3] * 0.125f + mv1;
            cm0 = fmaxf(cm0, fmaxf(cS[nt][0], cS[nt][1]));
            cm1 = fmaxf(cm1, fmaxf(cS[nt][2], cS[nt][3]));
        }
#pragma unroll
        for (int off = 1; off <= 2; off <<= 1) {
            cm0 = fmaxf(cm0, __shfl_xor_sync(0xFFFFFFFFu, cm0, off));
            cm1 = fmaxf(cm1, __shfl_xor_sync(0xFFFFFFFFu, cm1, off));
        }

        const float mn0 = fmaxf(m0, cm0);
        const float mn1 = fmaxf(m1, cm1);
        const float a0  = __expf(m0 - mn0);
        const float a1  = __expf(m1 - mn1);
        m0 = mn0; m1 = mn1;

        float s0 = 0.f, s1 = 0.f;
#pragma unroll
        for (int nt = 0; nt < 8; nt++) {
            cS[nt][0] = __expf(cS[nt][0] - mn0);
            cS[nt][1] = __expf(cS[nt][1] - mn0);
            cS[nt][2] = __expf(cS[nt][2] - mn1);
            cS[nt][3] = __expf(cS[nt][3] - mn1);
            s0 += cS[nt][0] + cS[nt][1];
            s1 += cS[nt][2] + cS[nt][3];
        }
#pragma unroll
        for (int off = 1; off <= 2; off <<= 1) {
            s0 += __shfl_xor_sync(0xFFFFFFFFu, s0, off);
            s1 += __shfl_xor_sync(0xFFFFFFFFu, s1, off);
        }
        l0 = l0 * a0 + s0;
        l1 = l1 * a1 + s1;

#pragma unroll
        for (int dt = 0; dt < 8; dt++) {
            o[dt][0] *= a0; o[dt][1] *= a0;
            o[dt][2] *= a1; o[dt][3] *= a1;
        }

#pragma unroll
        for (int kt = 0; kt < 8; kt++) {
            const int sl0 = qb + (lq >> 1);
            const int sl1 = sl0 + 2;
            const bool odd = lq & 1;
            float t00 = __shfl_sync(0xFFFFFFFFu, cS[kt][0], sl0);
            float t10 = __shfl_sync(0xFFFFFFFFu, cS[kt][1], sl0);
            float t01 = __shfl_sync(0xFFFFFFFFu, cS[kt][0], sl1);
            float t11 = __shfl_sync(0xFFFFFFFFu, cS[kt][1], sl1);
            float u00 = __shfl_sync(0xFFFFFFFFu, cS[kt][2], sl0);
            float u10 = __shfl_sync(0xFFFFFFFFu, cS[kt][3], sl0);
            float u01 = __shfl_sync(0xFFFFFFFFu, cS[kt][2], sl1);
            float u11 = __shfl_sync(0xFFFFFFFFu, cS[kt][3], sl1);
            uint32_t pa[4];
            pa[0] = f2tf(odd ? t10 : t00);
            pa[1] = f2tf(odd ? u10 : u00);
            pa[2] = f2tf(odd ? t11 : t01);
            pa[3] = f2tf(odd ? u11 : u01);
#pragma unroll
            for (int dt = 0; dt < 8; dt++) {
                uint32_t b0 = f2tf(V[(kt * 8 + lq) * KV_LD + dt * 8 + lr]);
                uint32_t b1 = f2tf(V[(kt * 8 + 4 + lq) * KV_LD + dt * 8 + lr]);
                MMA_TF32(o[dt], pa, b0, b1);
            }
        }
        __syncthreads();
    }

    {
        const float r0 = 1.f / l0;
        const float r1 = 1.f / l1;
        const int r = w * 16 + lr;
        float* ob0 = outctx + ((size_t)b * NS + r) * NHID + h * HD;
        float* ob1 = outctx + ((size_t)b * NS + r + 8) * NHID + h * HD;
#pragma unroll
        for (int dt = 0; dt < 8; dt++) {
            const int dcol = dt * 8 + 2 * lq;
            float2 v0, v1;
            v0.x = o[dt][0] * r0; v0.y = o[dt][1] * r0;
            v1.x = o[dt][2] * r1; v1.y = o[dt][3] * r1;
            *(float2*)&ob0[dcol] = v0;
            *(float2*)&ob1[dcol] = v1;
        }
    }
}

// =====================================================================
// Host launcher
// =====================================================================
extern "C" void kernel_launch(void* const* d_in, const int* in_sizes, int n_in,
                              void* d_out, int out_size)
{
    const float* hidden = (const float*)d_in[0];
    const float* mask   = (const float*)d_in[1];
    const float* Wq     = (const float*)d_in[2];
    const float* bq     = (const float*)d_in[3];
    const float* Wk     = (const float*)d_in[4];
    const float* bk     = (const float*)d_in[5];
    const float* Wv     = (const float*)d_in[6];
    const float* bv     = (const float*)d_in[7];
    const float* c0k    = (const float*)d_in[8];
    const float* c0v    = (const float*)d_in[9];
    const float* c1k    = (const float*)d_in[10];
    const float* c1v    = (const float*)d_in[11];

    float* out   = (float*)d_out;
    const size_t sect = (size_t)NB * NS * NHID;
    float* out_k = out + sect;
    float* out_v = out + 2 * sect;

    // resolve device-global scratch addresses
    float *hid_d, *w_d;
    cudaGetSymbolAddress((void**)&hid_d, g_hid);
    cudaGetSymbolAddress((void**)&w_d,   g_w);

    const int gemm_smem = 3 * STAGE * 4;            // 82944
    const int attn_smem = (4 * KV_TILE + LTOT) * 4; // 71936

    cudaFuncSetAttribute(qkv_gemm_tc2,
                         cudaFuncAttributeMaxDynamicSharedMemorySize, gemm_smem);
    cudaFuncSetAttribute(attn_flash,
                         cudaFuncAttributeMaxDynamicSharedMemorySize, attn_smem);

    // pre-round hidden + weights to tf32
    const int nh4 = (NB * NS * NHID) / 4;           // 2,949,120
    const int nw4 = (NHID * NHID) / 4;              // 147,456
    round_tf32_kernel<<<1536, 256>>>((const float4*)hidden, (float4*)hid_d, nh4);
    round_tf32_kernel<<<288, 256>>>((const float4*)Wq, (float4*)(w_d), nw4);
    round_tf32_kernel<<<288, 256>>>((const float4*)Wk, (float4*)(w_d + (size_t)NHID * NHID), nw4);
    round_tf32_kernel<<<288, 256>>>((const float4*)Wv, (float4*)(w_d + (size_t)2 * NHID * NHID), nw4);

    dim3 ggrid(NB * NS / 128, 3 * NHID / 64);       // (120, 36)
    qkv_gemm_tc2<<<ggrid, 256, gemm_smem>>>(bq, bk, bv, out_k, out_v);

    attn_flash<<<NB * NH, 128, attn_smem>>>(mask, c0k, c0v, c1k, c1v,
                                            out_k, out_v, out);
}

// round 5
// speedup vs baseline: 1.0059x; 1.0059x over previous
#include <cuda_runtime.h>
#include <cstdint>

// ---------------- problem constants (fixed by the dataset) ----------------
#define NB    240
#define NS    64
#define NHID  768
#define NH    12
#define HD    64
#define L0    384
#define L1    128
#define LTOT  576
#define NCHUNK 9

// device-global scratch (allocation-free), all tf32-rounded copies
__device__ float g_q   [(size_t)NB * NH * NS * HD];
__device__ float g_hid [(size_t)NB * NS * NHID];
__device__ float g_w   [(size_t)3 * NHID * NHID];
__device__ float g_kr  [(size_t)NB * NH * NS * HD];
__device__ float g_vr  [(size_t)NB * NH * NS * HD];
__device__ float g_c0kr[(size_t)8 * NH * L0 * HD];
__device__ float g_c0vr[(size_t)8 * NH * L0 * HD];

// ---------------- tf32 helpers ----------------
__device__ __forceinline__ uint32_t f2tf(float x) {
    uint32_t r;
    asm("cvt.rna.tf32.f32 %0, %1;" : "=r"(r) : "f"(x));
    return r;
}
__device__ __forceinline__ float f2tf_f(float x) { return __uint_as_float(f2tf(x)); }
__device__ __forceinline__ uint32_t fu(float x) { return __float_as_uint(x); }

#define MMA_TF32(c, a, b0, b1)                                              \
    asm volatile(                                                           \
        "mma.sync.aligned.m16n8k8.row.col.f32.tf32.tf32.f32 "               \
        "{%0,%1,%2,%3}, {%4,%5,%6,%7}, {%8,%9}, {%0,%1,%2,%3};\n"           \
        : "+f"((c)[0]), "+f"((c)[1]), "+f"((c)[2]), "+f"((c)[3])            \
        : "r"((a)[0]), "r"((a)[1]), "r"((a)[2]), "r"((a)[3]),               \
          "r"(b0), "r"(b1))

__device__ __forceinline__ void cp16(float* dst, const float* src) {
    uint32_t d = (uint32_t)__cvta_generic_to_shared(dst);
    asm volatile("cp.async.cg.shared.global [%0], [%1], 16;\n"
                 :: "r"(d), "l"(src));
}
__device__ __forceinline__ void cp_commit() {
    asm volatile("cp.async.commit_group;\n");
}
template <int N> __device__ __forceinline__ void cp_wait() {
    asm volatile("cp.async.wait_group %0;\n" :: "n"(N));
}

// =====================================================================
// Elementwise tf32 rounding (RNA) src -> dst, float4-vectorized.
// =====================================================================
__global__ __launch_bounds__(256) void round_tf32_kernel(
    const float4* __restrict__ src, float4* __restrict__ dst, int n4)
{
    int i = blockIdx.x * blockDim.x + threadIdx.x;
    const int stride = gridDim.x * blockDim.x;
    for (; i < n4; i += stride) {
        float4 v = src[i];
        v.x = f2tf_f(v.x); v.y = f2tf_f(v.y);
        v.z = f2tf_f(v.z); v.w = f2tf_f(v.w);
        dst[i] = v;
    }
}

// =====================================================================
// QKV projection, tf32 mma, 2-stage cp.async pipeline (55 KB smem ->
// 3 blocks/SM). Inputs pre-rounded tf32 -> raw-bit fragment loads.
// Block tile 128x64, BK=32, 256 thr = 8 warps (4x2), warp tile 32x32.
// =====================================================================
#define GLD   36
#define A_SZ  (128 * GLD)
#define B_SZ  (64 * GLD)
#define STAGE (A_SZ + B_SZ)

__global__ __launch_bounds__(256, 3) void qkv_gemm_tc2(
    const float* __restrict__ bq, const float* __restrict__ bk_,
    const float* __restrict__ bv,
    float* __restrict__ out_k, float* __restrict__ out_v)
{
    extern __shared__ float smg[];

    const int m0  = blockIdx.x * 128;
    const int n0g = blockIdx.y * 64;
    const int mat = n0g / NHID;
    const int n0  = n0g - mat * NHID;

    const float* Ag = g_hid;
    const float* Bg = g_w + (size_t)mat * NHID * NHID;
    const float* bi = (mat == 0) ? bq : (mat == 1) ? bk_ : bv;

    const int tid  = threadIdx.x;
    const int lane = tid & 31;
    const int w    = tid >> 5;
    const int wm   = w & 3;
    const int wn   = w >> 2;
    const int lq   = lane & 3;
    const int lr   = lane >> 2;

    // async-load mapping
    const int arow = tid >> 1;
    const int acb  = (tid & 1) * 16;
    const int brow = tid >> 2;
    const int bcb  = (tid & 3) * 8;

    auto load_stage = [&](int s, int k0) {
        float* A = smg + s * STAGE;
        float* B = A + A_SZ;
        const float* ag = Ag + (size_t)(m0 + arow) * NHID + k0 + acb;
        const float* bg = Bg + (size_t)(n0 + brow) * NHID + k0 + bcb;
        float* ad = A + arow * GLD + acb;
        float* bd = B + brow * GLD + bcb;
        cp16(ad + 0,  ag + 0);
        cp16(ad + 4,  ag + 4);
        cp16(ad + 8,  ag + 8);
        cp16(ad + 12, ag + 12);
        cp16(bd + 0,  bg + 0);
        cp16(bd + 4,  bg + 4);
    };

    float acc[2][4][4];
#pragma unroll
    for (int mt = 0; mt < 2; mt++)
#pragma unroll
        for (int nt = 0; nt < 4; nt++)
#pragma unroll
            for (int i = 0; i < 4; i++) acc[mt][nt][i] = 0.f;

    auto compute = [&](int s) {
        const float* A = smg + s * STAGE;
        const float* B = A + A_SZ;
#pragma unroll
        for (int ks = 0; ks < 4; ks++) {
            const int kb = ks * 8;
            uint32_t af[2][4];
#pragma unroll
            for (int mt = 0; mt < 2; mt++) {
                const int r = wm * 32 + mt * 16 + lr;
                af[mt][0] = fu(A[r * GLD + kb + lq]);
                af[mt][1] = fu(A[(r + 8) * GLD + kb + lq]);
                af[mt][2] = fu(A[r * GLD + kb + 4 + lq]);
                af[mt][3] = fu(A[(r + 8) * GLD + kb + 4 + lq]);
            }
            uint32_t bf[4][2];
#pragma unroll
            for (int nt = 0; nt < 4; nt++) {
                const int n = wn * 32 + nt * 8 + lr;
                bf[nt][0] = fu(B[n * GLD + kb + lq]);
                bf[nt][1] = fu(B[n * GLD + kb + 4 + lq]);
            }
#pragma unroll
            for (int mt = 0; mt < 2; mt++)
#pragma unroll
                for (int nt = 0; nt < 4; nt++)
                    MMA_TF32(acc[mt][nt], af[mt], bf[nt][0], bf[nt][1]);
        }
    };

    // 2-stage pipeline: load(it+1) flies while compute(it) runs.
    load_stage(0, 0);
    cp_commit();
    for (int it = 0; it < 24; it++) {
        cp_wait<0>();
        __syncthreads();           // data visible + buffer (it&1)^1 free
        if (it + 1 < 24) {
            load_stage((it + 1) & 1, (it + 1) * 32);
            cp_commit();
        }
        compute(it & 1);
    }

    // epilogue: bias + scatter to [b, h, s, d]
    float* dst  = (mat == 0) ? g_q  : (mat == 1) ? out_k : out_v;
    float* dstr = (mat == 0) ? 0    : (mat == 1) ? g_kr  : g_vr;
#pragma unroll
    for (int nt = 0; nt < 4; nt++) {
        const int ncol = n0 + wn * 32 + nt * 8 + 2 * lq;
        const float b0 = bi[ncol];
        const float b1 = bi[ncol + 1];
        const int h = ncol >> 6;
        const int d = ncol & 63;
#pragma unroll
        for (int mt = 0; mt < 2; mt++) {
            const int r = wm * 32 + mt * 16 + lr;
#pragma unroll
            for (int half = 0; half < 2; half++) {
                const int m = m0 + r + 8 * half;
                const int b = m >> 6;
                const int s = m & 63;
                const size_t idx = (((size_t)b * NH + h) * NS + s) * HD + d;
                float2 v;
                v.x = acc[mt][nt][2 * half + 0] + b0;
                v.y = acc[mt][nt][2 * half + 1] + b1;
                if (mat == 0) {
                    v.x = f2tf_f(v.x); v.y = f2tf_f(v.y);
                    *(float2*)&dst[idx] = v;
                } else {
                    *(float2*)&dst[idx] = v;            // exact output
                    float2 vr;
                    vr.x = f2tf_f(v.x); vr.y = f2tf_f(v.y);
                    *(float2*)&dstr[idx] = vr;          // rounded copy
                }
            }
        }
    }
}

// =====================================================================
// Flash cache attention, tf32 mma. Chunks 0-5 (c0 rounded scratch) and
// 8 (g_kr/g_vr) are pre-rounded -> raw-bit loads. Chunks 6,7 (c1) get
// an in-smem rounding sweep after cp.async lands.
// =====================================================================
#define KV_LD 68
#define KV_TILE (64 * KV_LD)

__global__ __launch_bounds__(128, 3) void attn_flash(
    const float* __restrict__ mask,
    const float* __restrict__ c1k, const float* __restrict__ c1v,
    float* __restrict__ outctx)
{
    extern __shared__ float sm[];
    float* kbuf   = sm;                       // [2][64][68]
    float* vbuf   = kbuf + 2 * KV_TILE;       // [2][64][68]
    float* mask_s = vbuf + 2 * KV_TILE;       // [576]

    const int bh   = blockIdx.x;
    const int b    = bh / NH;
    const int h    = bh - b * NH;
    const int tid  = threadIdx.x;
    const int lane = tid & 31;
    const int w    = tid >> 5;
    const int lq   = lane & 3;
    const int lr   = lane >> 2;
    const int qb   = lane & 28;

    const float* c0kb = g_c0kr + ((size_t)(b & 7) * NH + h) * L0 * HD;
    const float* c0vb = g_c0vr + ((size_t)(b & 7) * NH + h) * L0 * HD;
    const float* c1kb = c1k + (size_t)bh * L1 * HD;
    const float* c1vb = c1v + (size_t)bh * L1 * HD;
    const float* ksb  = g_kr + (size_t)bh * NS * HD;
    const float* vsb  = g_vr + (size_t)bh * NS * HD;

    auto ksrc_of = [&](int c) -> const float* {
        return (c < 6) ? (c0kb + c * 64 * HD)
             : (c < 8) ? (c1kb + (c - 6) * 64 * HD) : ksb;
    };
    auto vsrc_of = [&](int c) -> const float* {
        return (c < 6) ? (c0vb + c * 64 * HD)
             : (c < 8) ? (c1vb + (c - 6) * 64 * HD) : vsb;
    };

    auto load_tile = [&](float* buf, const float* src) {
        const int r  = tid >> 1;
        const int c0 = (tid & 1) * 32;
        float* d = buf + r * KV_LD + c0;
        const float* s = src + r * HD + c0;
#pragma unroll
        for (int i = 0; i < 8; i++) cp16(d + 4 * i, s + 4 * i);
    };
    // in-place tf32 rounding of a freshly-landed tile (c1 chunks only)
    auto round_tile = [&](float* buf) {
        const int r  = tid >> 1;
        const int c0 = (tid & 1) * 32;
        float* d = buf + r * KV_LD + c0;
#pragma unroll
        for (int i = 0; i < 8; i++) {
            float4 v = *(float4*)(d + 4 * i);
            v.x = f2tf_f(v.x); v.y = f2tf_f(v.y);
            v.z = f2tf_f(v.z); v.w = f2tf_f(v.w);
            *(float4*)(d + 4 * i) = v;
        }
    };

    // prologue: Q -> kbuf[1]; chunk0 -> buf0; mask
    load_tile(kbuf + KV_TILE, g_q + (size_t)bh * NS * HD);
    cp_commit();
    load_tile(kbuf, ksrc_of(0));
    load_tile(vbuf, vsrc_of(0));
    cp_commit();

    for (int i = tid; i < LTOT; i += 128)
        mask_s[i] = mask[(size_t)b * LTOT + i];

    cp_wait<1>();
    __syncthreads();

    uint32_t qa[8][4];
    {
        const float* qs = kbuf + KV_TILE;
        const int r = w * 16 + lr;
#pragma unroll
        for (int ks = 0; ks < 8; ks++) {
            qa[ks][0] = fu(qs[r * KV_LD + ks * 8 + lq]);
            qa[ks][1] = fu(qs[(r + 8) * KV_LD + ks * 8 + lq]);
            qa[ks][2] = fu(qs[r * KV_LD + ks * 8 + 4 + lq]);
            qa[ks][3] = fu(qs[(r + 8) * KV_LD + ks * 8 + 4 + lq]);
        }
    }
    __syncthreads();

    float m0 = -1e30f, m1 = -1e30f;
    float l0 = 0.f,    l1 = 0.f;
    float o[8][4];
#pragma unroll
    for (int dt = 0; dt < 8; dt++)
#pragma unroll
        for (int i = 0; i < 4; i++) o[dt][i] = 0.f;

    for (int c = 0; c < NCHUNK; c++) {
        if (c < NCHUNK - 1) {
            float* kb = kbuf + ((c + 1) & 1) * KV_TILE;
            float* vb = vbuf + ((c + 1) & 1) * KV_TILE;
            load_tile(kb, ksrc_of(c + 1));
            load_tile(vb, vsrc_of(c + 1));
            cp_commit();
            cp_wait<1>();
        } else {
            cp_wait<0>();
        }
        __syncthreads();

        float* K = kbuf + (c & 1) * KV_TILE;
        float* V = vbuf + (c & 1) * KV_TILE;

        if (c == 6 || c == 7) {       // c1 chunks arrive unrounded
            round_tile(K);
            round_tile(V);
            __syncthreads();
        }

        float cS[8][4];
#pragma unroll
        for (int nt = 0; nt < 8; nt++)
#pragma unroll
            for (int i = 0; i < 4; i++) cS[nt][i] = 0.f;

#pragma unroll
        for (int ks = 0; ks < 8; ks++) {
#pragma unroll
            for (int nt = 0; nt < 8; nt++) {
                const int n = nt * 8 + lr;
                uint32_t b0 = fu(K[n * KV_LD + ks * 8 + lq]);
                uint32_t b1 = fu(K[n * KV_LD + ks * 8 + 4 + lq]);
                MMA_TF32(cS[nt], qa[ks], b0, b1);
            }
        }

        float cm0 = -1e30f, cm1 = -1e30f;
#pragma unroll
        for (int nt = 0; nt < 8; nt++) {
            const int col = c * 64 + nt * 8 + 2 * lq;
            const float mv0 = mask_s[col];
            const float mv1 = mask_s[col + 1];
            cS[nt][0] = cS[nt][0] * 0.125f + mv0;
            cS[nt][1] = cS[nt][1] * 0.125f + mv1;
            cS[nt][2] = cS[nt][2] * 0.125f + mv0;
            cS[nt][3] = cS[nt][3] * 0.125f + mv1;
            cm0 = fmaxf(cm0, fmaxf(cS[nt][0], cS[nt][1]));
            cm1 = fmaxf(cm1, fmaxf(cS[nt][2], cS[nt][3]));
        }
#pragma unroll
        for (int off = 1; off <= 2; off <<= 1) {
            cm0 = fmaxf(cm0, __shfl_xor_sync(0xFFFFFFFFu, cm0, off));
            cm1 = fmaxf(cm1, __shfl_xor_sync(0xFFFFFFFFu, cm1, off));
        }

        const float mn0 = fmaxf(m0, cm0);
        const float mn1 = fmaxf(m1, cm1);
        const float a0  = __expf(m0 - mn0);
        const float a1  = __expf(m1 - mn1);
        m0 = mn0; m1 = mn1;

        float s0 = 0.f, s1 = 0.f;
#pragma unroll
        for (int nt = 0; nt < 8; nt++) {
            cS[nt][0] = __expf(cS[nt][0] - mn0);
            cS[nt][1] = __expf(cS[nt][1] - mn0);
            cS[nt][2] = __expf(cS[nt][2] - mn1);
            cS[nt][3] = __expf(cS[nt][3] - mn1);
            s0 += cS[nt][0] + cS[nt][1];
            s1 += cS[nt][2] + cS[nt][3];
        }
#pragma unroll
        for (int off = 1; off <= 2; off <<= 1) {
            s0 += __shfl_xor_sync(0xFFFFFFFFu, s0, off);
            s1 += __shfl_xor_sync(0xFFFFFFFFu, s1, off);
        }
        l0 = l0 * a0 + s0;
        l1 = l1 * a1 + s1;

#pragma unroll
        for (int dt = 0; dt < 8; dt++) {
            o[dt][0] *= a0; o[dt][1] *= a0;
            o[dt][2] *= a1; o[dt][3] *= a1;
        }

#pragma unroll
        for (int kt = 0; kt < 8; kt++) {
            const int sl0 = qb + (lq >> 1);
            const int sl1 = sl0 + 2;
            const bool odd = lq & 1;
            float t00 = __shfl_sync(0xFFFFFFFFu, cS[kt][0], sl0);
            float t10 = __shfl_sync(0xFFFFFFFFu, cS[kt][1], sl0);
            float t01 = __shfl_sync(0xFFFFFFFFu, cS[kt][0], sl1);
            float t11 = __shfl_sync(0xFFFFFFFFu, cS[kt][1], sl1);
            float u00 = __shfl_sync(0xFFFFFFFFu, cS[kt][2], sl0);
            float u10 = __shfl_sync(0xFFFFFFFFu, cS[kt][3], sl0);
            float u01 = __shfl_sync(0xFFFFFFFFu, cS[kt][2], sl1);
            float u11 = __shfl_sync(0xFFFFFFFFu, cS[kt][3], sl1);
            uint32_t pa[4];
            pa[0] = f2tf(odd ? t10 : t00);
            pa[1] = f2tf(odd ? u10 : u00);
            pa[2] = f2tf(odd ? t11 : t01);
            pa[3] = f2tf(odd ? u11 : u01);
#pragma unroll
            for (int dt = 0; dt < 8; dt++) {
                uint32_t b0 = fu(V[(kt * 8 + lq) * KV_LD + dt * 8 + lr]);
                uint32_t b1 = fu(V[(kt * 8 + 4 + lq) * KV_LD + dt * 8 + lr]);
                MMA_TF32(o[dt], pa, b0, b1);
            }
        }
        __syncthreads();
    }

    {
        const float r0 = 1.f / l0;
        const float r1 = 1.f / l1;
        const int r = w * 16 + lr;
        float* ob0 = outctx + ((size_t)b * NS + r) * NHID + h * HD;
        float* ob1 = outctx + ((size_t)b * NS + r + 8) * NHID + h * HD;
#pragma unroll
        for (int dt = 0; dt < 8; dt++) {
            const int dcol = dt * 8 + 2 * lq;
            float2 v0, v1;
            v0.x = o[dt][0] * r0; v0.y = o[dt][1] * r0;
            v1.x = o[dt][2] * r1; v1.y = o[dt][3] * r1;
            *(float2*)&ob0[dcol] = v0;
            *(float2*)&ob1[dcol] = v1;
        }
    }
}

// =====================================================================
// Host launcher
// =====================================================================
extern "C" void kernel_launch(void* const* d_in, const int* in_sizes, int n_in,
                              void* d_out, int out_size)
{
    const float* hidden = (const float*)d_in[0];
    const float* mask   = (const float*)d_in[1];
    const float* Wq     = (const float*)d_in[2];
    const float* bq     = (const float*)d_in[3];
    const float* Wk     = (const float*)d_in[4];
    const float* bk     = (const float*)d_in[5];
    const float* Wv     = (const float*)d_in[6];
    const float* bv     = (const float*)d_in[7];
    const float* c0k    = (const float*)d_in[8];
    const float* c0v    = (const float*)d_in[9];
    const float* c1k    = (const float*)d_in[10];
    const float* c1v    = (const float*)d_in[11];

    float* out   = (float*)d_out;
    const size_t sect = (size_t)NB * NS * NHID;
    float* out_k = out + sect;
    float* out_v = out + 2 * sect;

    float *hid_d, *w_d, *c0k_d, *c0v_d;
    cudaGetSymbolAddress((void**)&hid_d,  g_hid);
    cudaGetSymbolAddress((void**)&w_d,    g_w);
    cudaGetSymbolAddress((void**)&c0k_d,  g_c0kr);
    cudaGetSymbolAddress((void**)&c0v_d,  g_c0vr);

    const int gemm_smem = 2 * STAGE * 4;            // 55296
    const int attn_smem = (4 * KV_TILE + LTOT) * 4; // 71936

    cudaFuncSetAttribute(qkv_gemm_tc2,
                         cudaFuncAttributeMaxDynamicSharedMemorySize, gemm_smem);
    cudaFuncSetAttribute(attn_flash,
                         cudaFuncAttributeMaxDynamicSharedMemorySize, attn_smem);

    // pre-round to tf32: hidden, weights, c0 caches
    const int nh4 = (NB * NS * NHID) / 4;           // 2,949,120
    const int nw4 = (NHID * NHID) / 4;              // 147,456
    const int nc4 = (8 * NH * L0 * HD) / 4;         // 589,824
    round_tf32_kernel<<<1536, 256>>>((const float4*)hidden, (float4*)hid_d, nh4);
    round_tf32_kernel<<<288, 256>>>((const float4*)Wq, (float4*)(w_d), nw4);
    round_tf32_kernel<<<288, 256>>>((const float4*)Wk, (float4*)(w_d + (size_t)NHID * NHID), nw4);
    round_tf32_kernel<<<288, 256>>>((const float4*)Wv, (float4*)(w_d + (size_t)2 * NHID * NHID), nw4);
    round_tf32_kernel<<<576, 256>>>((const float4*)c0k, (float4*)c0k_d, nc4);
    round_tf32_kernel<<<576, 256>>>((const float4*)c0v, (float4*)c0v_d, nc4);

    dim3 ggrid(NB * NS / 128, 3 * NHID / 64);       // (120, 36)
    qkv_gemm_tc2<<<ggrid, 256, gemm_smem>>>(bq, bk, bv, out_k, out_v);

    attn_flash<<<NB * NH, 128, attn_smem>>>(mask, c1k, c1v, out);
}

// round 7
// speedup vs baseline: 1.0821x; 1.0757x over previous
#include <cuda_runtime.h>
#include <cstdint>

// ---------------- problem constants (fixed by the dataset) ----------------
#define NB    240
#define NS    64
#define NHID  768
#define NH    12
#define HD    64
#define L0    384
#define L1    128
#define LTOT  576
#define NCHUNK 9

// device-global scratch (allocation-free)
__device__ float g_q  [(size_t)NB * NH * NS * HD];   // q, tf32-rounded
__device__ float g_hid[(size_t)NB * NS * NHID];      // hidden, tf32-rounded
__device__ float g_w  [(size_t)3 * NHID * NHID];     // Wq|Wk|Wv, tf32-rounded

// ---------------- tf32 helpers ----------------
__device__ __forceinline__ uint32_t f2tf(float x) {
    uint32_t r;
    asm("cvt.rna.tf32.f32 %0, %1;" : "=r"(r) : "f"(x));
    return r;
}
__device__ __forceinline__ float f2tf_f(float x) { return __uint_as_float(f2tf(x)); }
__device__ __forceinline__ uint32_t fu(float x) { return __float_as_uint(x); }

#define MMA_TF32(c, a, b0, b1)                                              \
    asm volatile(                                                           \
        "mma.sync.aligned.m16n8k8.row.col.f32.tf32.tf32.f32 "               \
        "{%0,%1,%2,%3}, {%4,%5,%6,%7}, {%8,%9}, {%0,%1,%2,%3};\n"           \
        : "+f"((c)[0]), "+f"((c)[1]), "+f"((c)[2]), "+f"((c)[3])            \
        : "r"((a)[0]), "r"((a)[1]), "r"((a)[2]), "r"((a)[3]),               \
          "r"(b0), "r"(b1))

__device__ __forceinline__ void cp16(float* dst, const float* src) {
    uint32_t d = (uint32_t)__cvta_generic_to_shared(dst);
    asm volatile("cp.async.cg.shared.global [%0], [%1], 16;\n" :: "r"(d), "l"(src));
}
__device__ __forceinline__ void cp_commit() {
    asm volatile("cp.async.commit_group;\n");
}
template <int N> __device__ __forceinline__ void cp_wait() {
    asm volatile("cp.async.wait_group %0;\n" :: "n"(N));
}

// =====================================================================
// Elementwise tf32 rounding (RNA) src -> dst
// =====================================================================
__global__ __launch_bounds__(256) void round_tf32_kernel(
    const float4* __restrict__ src, float4* __restrict__ dst, int n4)
{
    int i = blockIdx.x * blockDim.x + threadIdx.x;
    const int stride = gridDim.x * blockDim.x;
    for (; i < n4; i += stride) {
        float4 v = src[i];
        v.x = f2tf_f(v.x); v.y = f2tf_f(v.y);
        v.z = f2tf_f(v.z); v.w = f2tf_f(v.w);
        dst[i] = v;
    }
}

// =====================================================================
// QKV projection, tf32 legacy mma.
// Block tile 128x128, BK=32, 256 thr = 8 warps (4x2), warp tile 32x64.
// Register-staged global->smem double buffer (round-3 proven pattern),
// inputs pre-rounded -> no cvt in the loop, float4 direct STS.
// ld = 36 (=4 mod 32) -> conflict-free fragment LDS.
// =====================================================================
#define GLD   36
#define A_SZ  (128 * GLD)
#define B_SZ  (128 * GLD)
#define STAGE (A_SZ + B_SZ)

__global__ __launch_bounds__(256) void qkv_gemm_tc3(
    const float* __restrict__ bq, const float* __restrict__ bk_,
    const float* __restrict__ bv,
    float* __restrict__ out_k, float* __restrict__ out_v)
{
    extern __shared__ float smg[];

    const int m0  = blockIdx.x * 128;
    const int n0g = blockIdx.y * 128;          // 0..2303 step 128
    const int mat = n0g / NHID;                // 0=q 1=k 2=v (768/128=6 tiles/mat)
    const int n0  = n0g - mat * NHID;

    const float* Ag = g_hid;
    const float* Bg = g_w + (size_t)mat * NHID * NHID;
    const float* bi = (mat == 0) ? bq : (mat == 1) ? bk_ : bv;

    const int tid  = threadIdx.x;
    const int lane = tid & 31;
    const int w    = tid >> 5;
    const int wm   = w & 3;                    // 0..3  (rows wm*32)
    const int wn   = w >> 2;                   // 0..1  (cols wn*64)
    const int lq   = lane & 3;
    const int lr   = lane >> 2;

    // staging mapping: row = tid>>1 (0..127), col base = (tid&1)*16
    const int srow = tid >> 1;
    const int scol = (tid & 1) * 16;

    const float* aptr = Ag + (size_t)(m0 + srow) * NHID + scol;
    const float* bptr = Bg + (size_t)(n0 + srow) * NHID + scol;

    float4 ra[4], rb[4];

    auto ldglob = [&](int k0) {
#pragma unroll
        for (int i = 0; i < 4; i++) {
            ra[i] = *(const float4*)(aptr + k0 + 4 * i);
            rb[i] = *(const float4*)(bptr + k0 + 4 * i);
        }
    };
    auto st_smem = [&](int buf) {
        float* A = smg + buf * STAGE;
        float* B = A + A_SZ;
        float* ad = A + srow * GLD + scol;
        float* bd = B + srow * GLD + scol;
#pragma unroll
        for (int i = 0; i < 4; i++) {
            *(float4*)(ad + 4 * i) = ra[i];
            *(float4*)(bd + 4 * i) = rb[i];
        }
    };

    float acc[2][8][4];
#pragma unroll
    for (int mt = 0; mt < 2; mt++)
#pragma unroll
        for (int nt = 0; nt < 8; nt++)
#pragma unroll
            for (int i = 0; i < 4; i++) acc[mt][nt][i] = 0.f;

    auto compute = [&](int buf) {
        const float* A = smg + buf * STAGE;
        const float* B = A + A_SZ;
#pragma unroll
        for (int ks = 0; ks < 4; ks++) {
            const int kb = ks * 8;
            uint32_t af[2][4];
#pragma unroll
            for (int mt = 0; mt < 2; mt++) {
                const int r = wm * 32 + mt * 16 + lr;
                af[mt][0] = fu(A[r * GLD + kb + lq]);
                af[mt][1] = fu(A[(r + 8) * GLD + kb + lq]);
                af[mt][2] = fu(A[r * GLD + kb + 4 + lq]);
                af[mt][3] = fu(A[(r + 8) * GLD + kb + 4 + lq]);
            }
            uint32_t bf[8][2];
#pragma unroll
            for (int nt = 0; nt < 8; nt++) {
                const int n = wn * 64 + nt * 8 + lr;
                bf[nt][0] = fu(B[n * GLD + kb + lq]);
                bf[nt][1] = fu(B[n * GLD + kb + 4 + lq]);
            }
#pragma unroll
            for (int mt = 0; mt < 2; mt++)
#pragma unroll
                for (int nt = 0; nt < 8; nt++)
                    MMA_TF32(acc[mt][nt], af[mt], bf[nt][0], bf[nt][1]);
        }
    };

    ldglob(0);
    st_smem(0);
    __syncthreads();

    for (int it = 0; it < 24; it++) {
        if (it < 23) ldglob((it + 1) * 32);
        compute(it & 1);
        if (it < 23) st_smem((it + 1) & 1);
        __syncthreads();
    }

    // epilogue: bias + scatter to [b, h, s, d]
    float* dst = (mat == 0) ? g_q : (mat == 1) ? out_k : out_v;
#pragma unroll
    for (int nt = 0; nt < 8; nt++) {
        const int ncol = n0 + wn * 64 + nt * 8 + 2 * lq;
        const float b0 = bi[ncol];
        const float b1 = bi[ncol + 1];
        const int h = ncol >> 6;
        const int d = ncol & 63;
#pragma unroll
        for (int mt = 0; mt < 2; mt++) {
            const int r = wm * 32 + mt * 16 + lr;
#pragma unroll
            for (int half = 0; half < 2; half++) {
                const int m = m0 + r + 8 * half;
                const int b = m >> 6;
                const int s = m & 63;
                const size_t idx = (((size_t)b * NH + h) * NS + s) * HD + d;
                float2 v;
                v.x = acc[mt][nt][2 * half + 0] + b0;
                v.y = acc[mt][nt][2 * half + 1] + b1;
                if (mat == 0) { v.x = f2tf_f(v.x); v.y = f2tf_f(v.y); }
                *(float2*)&dst[idx] = v;
            }
        }
    }
}

// =====================================================================
// Flash cache attention, tf32 legacy mma (proven round-3 kernel).
// =====================================================================
#define KV_LD 68
#define KV_TILE (64 * KV_LD)

__global__ __launch_bounds__(128, 3) void attn_flash(
    const float* __restrict__ mask,
    const float* __restrict__ c0k, const float* __restrict__ c0v,
    const float* __restrict__ c1k, const float* __restrict__ c1v,
    const float* __restrict__ kself, const float* __restrict__ vself,
    float* __restrict__ outctx)
{
    extern __shared__ float sm[];
    float* kbuf   = sm;
    float* vbuf   = kbuf + 2 * KV_TILE;
    float* mask_s = vbuf + 2 * KV_TILE;

    const int bh   = blockIdx.x;
    const int b    = bh / NH;
    const int h    = bh - b * NH;
    const int tid  = threadIdx.x;
    const int lane = tid & 31;
    const int w    = tid >> 5;
    const int lq   = lane & 3;
    const int lr   = lane >> 2;
    const int qb   = lane & 28;

    const float* c0kb = c0k + ((size_t)(b & 7) * NH + h) * L0 * HD;
    const float* c0vb = c0v + ((size_t)(b & 7) * NH + h) * L0 * HD;
    const float* c1kb = c1k + (size_t)bh * L1 * HD;
    const float* c1vb = c1v + (size_t)bh * L1 * HD;
    const float* ksb  = kself + (size_t)bh * NS * HD;
    const float* vsb  = vself + (size_t)bh * NS * HD;

    auto ksrc_of = [&](int c) -> const float* {
        return (c < 6) ? (c0kb + c * 64 * HD)
             : (c < 8) ? (c1kb + (c - 6) * 64 * HD) : ksb;
    };
    auto vsrc_of = [&](int c) -> const float* {
        return (c < 6) ? (c0vb + c * 64 * HD)
             : (c < 8) ? (c1vb + (c - 6) * 64 * HD) : vsb;
    };

    auto load_tile = [&](float* buf, const float* src) {
        const int r  = tid >> 1;
        const int c0 = (tid & 1) * 32;
        float* d = buf + r * KV_LD + c0;
        const float* s = src + r * HD + c0;
#pragma unroll
        for (int i = 0; i < 8; i++) cp16(d + 4 * i, s + 4 * i);
    };

    load_tile(kbuf + KV_TILE, g_q + (size_t)bh * NS * HD);
    cp_commit();
    load_tile(kbuf, ksrc_of(0));
    load_tile(vbuf, vsrc_of(0));
    cp_commit();

    for (int i = tid; i < LTOT; i += 128)
        mask_s[i] = mask[(size_t)b * LTOT + i];

    cp_wait<1>();
    __syncthreads();

    uint32_t qa[8][4];
    {
        const float* qs = kbuf + KV_TILE;
        const int r = w * 16 + lr;
#pragma unroll
        for (int ks = 0; ks < 8; ks++) {
            qa[ks][0] = fu(qs[r * KV_LD + ks * 8 + lq]);
            qa[ks][1] = fu(qs[(r + 8) * KV_LD + ks * 8 + lq]);
            qa[ks][2] = fu(qs[r * KV_LD + ks * 8 + 4 + lq]);
            qa[ks][3] = fu(qs[(r + 8) * KV_LD + ks * 8 + 4 + lq]);
        }
    }
    __syncthreads();

    float m0 = -1e30f, m1 = -1e30f;
    float l0 = 0.f,    l1 = 0.f;
    float o[8][4];
#pragma unroll
    for (int dt = 0; dt < 8; dt++)
#pragma unroll
        for (int i = 0; i < 4; i++) o[dt][i] = 0.f;

    for (int c = 0; c < NCHUNK; c++) {
        if (c < NCHUNK - 1) {
            float* kb = kbuf + ((c + 1) & 1) * KV_TILE;
            float* vb = vbuf + ((c + 1) & 1) * KV_TILE;
            load_tile(kb, ksrc_of(c + 1));
            load_tile(vb, vsrc_of(c + 1));
            cp_commit();
            cp_wait<1>();
        } else {
            cp_wait<0>();
        }
        __syncthreads();

        const float* K = kbuf + (c & 1) * KV_TILE;
        const float* V = vbuf + (c & 1) * KV_TILE;

        float cS[8][4];
#pragma unroll
        for (int nt = 0; nt < 8; nt++)
#pragma unroll
            for (int i = 0; i < 4; i++) cS[nt][i] = 0.f;

#pragma unroll
        for (int ks = 0; ks < 8; ks++) {
#pragma unroll
            for (int nt = 0; nt < 8; nt++) {
                const int n = nt * 8 + lr;
                uint32_t b0 = f2tf(K[n * KV_LD + ks * 8 + lq]);
                uint32_t b1 = f2tf(K[n * KV_LD + ks * 8 + 4 + lq]);
                MMA_TF32(cS[nt], qa[ks], b0, b1);
            }
        }

        float cm0 = -1e30f, cm1 = -1e30f;
#pragma unroll
        for (int nt = 0; nt < 8; nt++) {
            const int col = c * 64 + nt * 8 + 2 * lq;
            const float mv0 = mask_s[col];
            const float mv1 = mask_s[col + 1];
            cS[nt][0] = cS[nt][0] * 0.125f + mv0;
            cS[nt][1] = cS[nt][1] * 0.125f + mv1;
            cS[nt][2] = cS[nt][2] * 0.125f + mv0;
            cS[nt][3] = cS[nt][3] * 0.125f + mv1;
            cm0 = fmaxf(cm0, fmaxf(cS[nt][0], cS[nt][1]));
            cm1 = fmaxf(cm1, fmaxf(cS[nt][2], cS[nt][3]));
        }
#pragma unroll
        for (int off = 1; off <= 2; off <<= 1) {
            cm0 = fmaxf(cm0, __shfl_xor_sync(0xFFFFFFFFu, cm0, off));
            cm1 = fmaxf(cm1, __shfl_xor_sync(0xFFFFFFFFu, cm1, off));
        }

        const float mn0 = fmaxf(m0, cm0);
        const float mn1 = fmaxf(m1, cm1);
        const float a0  = __expf(m0 - mn0);
        const float a1  = __expf(m1 - mn1);
        m0 = mn0; m1 = mn1;

        float s0 = 0.f, s1 = 0.f;
#pragma unroll
        for (int nt = 0; nt < 8; nt++) {
            cS[nt][0] = __expf(cS[nt][0] - mn0);
            cS[nt][1] = __expf(cS[nt][1] - mn0);
            cS[nt][2] = __expf(cS[nt][2] - mn1);
            cS[nt][3] = __expf(cS[nt][3] - mn1);
            s0 += cS[nt][0] + cS[nt][1];
            s1 += cS[nt][2] + cS[nt][3];
        }
#pragma unroll
        for (int off = 1; off <= 2; off <<= 1) {
            s0 += __shfl_xor_sync(0xFFFFFFFFu, s0, off);
            s1 += __shfl_xor_sync(0xFFFFFFFFu, s1, off);
        }
        l0 = l0 * a0 + s0;
        l1 = l1 * a1 + s1;

#pragma unroll
        for (int dt = 0; dt < 8; dt++) {
            o[dt][0] *= a0; o[dt][1] *= a0;
            o[dt][2] *= a1; o[dt][3] *= a1;
        }

#pragma unroll
        for (int kt = 0; kt < 8; kt++) {
            const int sl0 = qb + (lq >> 1);
            const int sl1 = sl0 + 2;
            const bool odd = lq & 1;
            float t00 = __shfl_sync(0xFFFFFFFFu, cS[kt][0], sl0);
            float t10 = __shfl_sync(0xFFFFFFFFu, cS[kt][1], sl0);
            float t01 = __shfl_sync(0xFFFFFFFFu, cS[kt][0], sl1);
            float t11 = __shfl_sync(0xFFFFFFFFu, cS[kt][1], sl1);
            float u00 = __shfl_sync(0xFFFFFFFFu, cS[kt][2], sl0);
            float u10 = __shfl_sync(0xFFFFFFFFu, cS[kt][3], sl0);
            float u01 = __shfl_sync(0xFFFFFFFFu, cS[kt][2], sl1);
            float u11 = __shfl_sync(0xFFFFFFFFu, cS[kt][3], sl1);
            uint32_t pa[4];
            pa[0] = f2tf(odd ? t10 : t00);
            pa[1] = f2tf(odd ? u10 : u00);
            pa[2] = f2tf(odd ? t11 : t01);
            pa[3] = f2tf(odd ? u11 : u01);
#pragma unroll
            for (int dt = 0; dt < 8; dt++) {
                uint32_t b0 = f2tf(V[(kt * 8 + lq) * KV_LD + dt * 8 + lr]);
                uint32_t b1 = f2tf(V[(kt * 8 + 4 + lq) * KV_LD + dt * 8 + lr]);
                MMA_TF32(o[dt], pa, b0, b1);
            }
        }
        __syncthreads();
    }

    {
        const float r0 = 1.f / l0;
        const float r1 = 1.f / l1;
        const int r = w * 16 + lr;
        float* ob0 = outctx + ((size_t)b * NS + r) * NHID + h * HD;
        float* ob1 = outctx + ((size_t)b * NS + r + 8) * NHID + h * HD;
#pragma unroll
        for (int dt = 0; dt < 8; dt++) {
            const int dcol = dt * 8 + 2 * lq;
            float2 v0, v1;
            v0.x = o[dt][0] * r0; v0.y = o[dt][1] * r0;
            v1.x = o[dt][2] * r1; v1.y = o[dt][3] * r1;
            *(float2*)&ob0[dcol] = v0;
            *(float2*)&ob1[dcol] = v1;
        }
    }
}

// =====================================================================
// Host launcher
// =====================================================================
extern "C" void kernel_launch(void* const* d_in, const int* in_sizes, int n_in,
                              void* d_out, int out_size)
{
    const float* hidden = (const float*)d_in[0];
    const float* mask   = (const float*)d_in[1];
    const float* Wq     = (const float*)d_in[2];
    const float* bq     = (const float*)d_in[3];
    const float* Wk     = (const float*)d_in[4];
    const float* bk     = (const float*)d_in[5];
    const float* Wv     = (const float*)d_in[6];
    const float* bv     = (const float*)d_in[7];
    const float* c0k    = (const float*)d_in[8];
    const float* c0v    = (const float*)d_in[9];
    const float* c1k    = (const float*)d_in[10];
    const float* c1v    = (const float*)d_in[11];

    float* out   = (float*)d_out;
    const size_t sect = (size_t)NB * NS * NHID;
    float* out_k = out + sect;
    float* out_v = out + 2 * sect;

    float *hid_d, *w_d;
    cudaGetSymbolAddress((void**)&hid_d, g_hid);
    cudaGetSymbolAddress((void**)&w_d,   g_w);

    const int gemm_smem = 2 * STAGE * 4;            // 73728
    const int attn_smem = (4 * KV_TILE + LTOT) * 4; // 71936

    cudaFuncSetAttribute(qkv_gemm_tc3,
                         cudaFuncAttributeMaxDynamicSharedMemorySize, gemm_smem);
    cudaFuncSetAttribute(attn_flash,
                         cudaFuncAttributeMaxDynamicSharedMemorySize, attn_smem);

    // pre-round hidden + weights (RNA) once
    const int nh4 = (NB * NS * NHID) / 4;
    const int nw4 = (NHID * NHID) / 4;
    round_tf32_kernel<<<2048, 256>>>((const float4*)hidden, (float4*)hid_d, nh4);
    round_tf32_kernel<<<288, 256>>>((const float4*)Wq, (float4*)(w_d), nw4);
    round_tf32_kernel<<<288, 256>>>((const float4*)Wk, (float4*)(w_d + (size_t)NHID * NHID), nw4);
    round_tf32_kernel<<<288, 256>>>((const float4*)Wv, (float4*)(w_d + (size_t)2 * NHID * NHID), nw4);

    dim3 ggrid(NB * NS / 128, 3 * NHID / 128);      // (120, 18)
    qkv_gemm_tc3<<<ggrid, 256, gemm_smem>>>(bq, bk, bv, out_k, out_v);

    attn_flash<<<NB * NH, 128, attn_smem>>>(mask, c0k, c0v, c1k, c1v,
                                            out_k, out_v, out);
}

// round 8
// speedup vs baseline: 1.4281x; 1.3198x over previous
#include <cuda_runtime.h>
#include <cuda_fp16.h>
#include <cstdint>

// ---------------- problem constants (fixed by the dataset) ----------------
#define NB    240
#define NS    64
#define NHID  768
#define NH    12
#define HD    64
#define L0    384
#define L1    128
#define LTOT  576
#define NCHUNK 9

// device-global scratch (allocation-free)
__device__ float  g_q   [(size_t)NB * NH * NS * HD];   // q, tf32-rounded
__device__ __half g_hidh[(size_t)NB * NS * NHID];      // hidden, fp16
__device__ __half g_wh  [(size_t)3 * NHID * NHID];     // Wq|Wk|Wv, fp16

// ---------------- helpers ----------------
__device__ __forceinline__ uint32_t f2tf(float x) {
    uint32_t r;
    asm("cvt.rna.tf32.f32 %0, %1;" : "=r"(r) : "f"(x));
    return r;
}
__device__ __forceinline__ float f2tf_f(float x) { return __uint_as_float(f2tf(x)); }
__device__ __forceinline__ uint32_t fu(float x) { return __float_as_uint(x); }

#define MMA_TF32(c, a, b0, b1)                                              \
    asm volatile(                                                           \
        "mma.sync.aligned.m16n8k8.row.col.f32.tf32.tf32.f32 "               \
        "{%0,%1,%2,%3}, {%4,%5,%6,%7}, {%8,%9}, {%0,%1,%2,%3};\n"           \
        : "+f"((c)[0]), "+f"((c)[1]), "+f"((c)[2]), "+f"((c)[3])            \
        : "r"((a)[0]), "r"((a)[1]), "r"((a)[2]), "r"((a)[3]),               \
          "r"(b0), "r"(b1))

#define MMA_F16(c, a, b0, b1)                                               \
    asm volatile(                                                           \
        "mma.sync.aligned.m16n8k16.row.col.f32.f16.f16.f32 "                \
        "{%0,%1,%2,%3}, {%4,%5,%6,%7}, {%8,%9}, {%0,%1,%2,%3};\n"           \
        : "+f"((c)[0]), "+f"((c)[1]), "+f"((c)[2]), "+f"((c)[3])            \
        : "r"((a)[0]), "r"((a)[1]), "r"((a)[2]), "r"((a)[3]),               \
          "r"(b0), "r"(b1))

__device__ __forceinline__ void cp16(float* dst, const float* src) {
    uint32_t d = (uint32_t)__cvta_generic_to_shared(dst);
    asm volatile("cp.async.cg.shared.global [%0], [%1], 16;\n" :: "r"(d), "l"(src));
}
__device__ __forceinline__ void cp_commit() {
    asm volatile("cp.async.commit_group;\n");
}
template <int N> __device__ __forceinline__ void cp_wait() {
    asm volatile("cp.async.wait_group %0;\n" :: "n"(N));
}

// =====================================================================
// float -> fp16 conversion, vectorized (float4 in, 8B out)
// =====================================================================
__global__ __launch_bounds__(256) void cvt_f16_kernel(
    const float4* __restrict__ src, uint2* __restrict__ dst, int n4)
{
    int i = blockIdx.x * blockDim.x + threadIdx.x;
    const int stride = gridDim.x * blockDim.x;
    for (; i < n4; i += stride) {
        float4 v = src[i];
        __half2 lo = __floats2half2_rn(v.x, v.y);
        __half2 hi = __floats2half2_rn(v.z, v.w);
        uint2 o;
        o.x = *(uint32_t*)&lo;
        o.y = *(uint32_t*)&hi;
        dst[i] = o;
    }
}

// =====================================================================
// QKV projection, fp16 mma (m16n8k16), fp32 accumulate.
// Block tile 128x64, BK=32, 256 thr = 8 warps (4x2), warp tile 32x32.
// Register-staged double buffer (round-3 proven loop structure).
// smem rows: 40 halves (20 words); word-stride 20 -> conflict-free
// fragment LDS (r*20+lq distinct mod 32 over r0..7 x lq0..3).
// =====================================================================
#define GLDW  20                      // 32-bit words per smem row
#define A_W   (128 * GLDW)            // 2560 words
#define B_W   (64 * GLDW)             // 1280 words
#define STAGEW (A_W + B_W)            // 3840 words = 15360 B

__global__ __launch_bounds__(256) void qkv_gemm_f16(
    const float* __restrict__ bq, const float* __restrict__ bk_,
    const float* __restrict__ bv,
    float* __restrict__ out_k, float* __restrict__ out_v)
{
    extern __shared__ uint32_t smw[];

    const int m0  = blockIdx.x * 128;
    const int n0g = blockIdx.y * 64;
    const int mat = n0g / NHID;
    const int n0  = n0g - mat * NHID;

    const __half* Ag = g_hidh;
    const __half* Bg = g_wh + (size_t)mat * NHID * NHID;
    const float*  bi = (mat == 0) ? bq : (mat == 1) ? bk_ : bv;

    const int tid  = threadIdx.x;
    const int lane = tid & 31;
    const int w    = tid >> 5;
    const int wm   = w & 3;           // m band (32 rows)
    const int wn   = w >> 2;          // n half (32 cols)
    const int lq   = lane & 3;
    const int lr   = lane >> 2;

    // staging: A = 512 16B units (2/thread), B = 256 units (1/thread)
    const int arow = tid >> 2;        // 0..63 (and +64)
    const int acu  = tid & 3;         // 16B unit within row (8 halves)

    uint4 ra[2], rb;

    auto ldglob = [&](int k0) {
        ra[0] = *(const uint4*)(Ag + (size_t)(m0 + arow) * NHID + k0 + acu * 8);
        ra[1] = *(const uint4*)(Ag + (size_t)(m0 + arow + 64) * NHID + k0 + acu * 8);
        rb    = *(const uint4*)(Bg + (size_t)(n0 + arow) * NHID + k0 + acu * 8);
    };
    auto st_smem = [&](int buf) {
        uint32_t* A = smw + buf * STAGEW;
        uint32_t* B = A + A_W;
        *(uint4*)(A + arow * GLDW + acu * 4)        = ra[0];
        *(uint4*)(A + (arow + 64) * GLDW + acu * 4) = ra[1];
        *(uint4*)(B + arow * GLDW + acu * 4)        = rb;
    };

    float acc[2][4][4];
#pragma unroll
    for (int mt = 0; mt < 2; mt++)
#pragma unroll
        for (int nt = 0; nt < 4; nt++)
#pragma unroll
            for (int i = 0; i < 4; i++) acc[mt][nt][i] = 0.f;

    auto compute = [&](int buf) {
        const uint32_t* A = smw + buf * STAGEW;
        const uint32_t* B = A + A_W;
#pragma unroll
        for (int ks = 0; ks < 2; ks++) {           // two k16 steps per BK=32
            const int kw = ks * 8;                 // word offset
            uint32_t af[2][4];
#pragma unroll
            for (int mt = 0; mt < 2; mt++) {
                const int r = wm * 32 + mt * 16 + lr;
                af[mt][0] = A[r * GLDW + kw + lq];
                af[mt][1] = A[(r + 8) * GLDW + kw + lq];
                af[mt][2] = A[r * GLDW + kw + 4 + lq];
                af[mt][3] = A[(r + 8) * GLDW + kw + 4 + lq];
            }
            uint32_t bf[4][2];
#pragma unroll
            for (int nt = 0; nt < 4; nt++) {
                const int n = wn * 32 + nt * 8 + lr;
                bf[nt][0] = B[n * GLDW + kw + lq];
                bf[nt][1] = B[n * GLDW + kw + 4 + lq];
            }
#pragma unroll
            for (int mt = 0; mt < 2; mt++)
#pragma unroll
                for (int nt = 0; nt < 4; nt++)
                    MMA_F16(acc[mt][nt], af[mt], bf[nt][0], bf[nt][1]);
        }
    };

    ldglob(0);
    st_smem(0);
    __syncthreads();

    for (int it = 0; it < 24; it++) {
        if (it < 23) ldglob((it + 1) * 32);
        compute(it & 1);
        if (it < 23) st_smem((it + 1) & 1);
        __syncthreads();
    }

    // epilogue: bias + scatter to [b, h, s, d]; q rounded to tf32
    float* dst = (mat == 0) ? g_q : (mat == 1) ? out_k : out_v;
#pragma unroll
    for (int nt = 0; nt < 4; nt++) {
        const int ncol = n0 + wn * 32 + nt * 8 + 2 * lq;
        const float b0 = bi[ncol];
        const float b1 = bi[ncol + 1];
        const int h = ncol >> 6;
        const int d = ncol & 63;
#pragma unroll
        for (int mt = 0; mt < 2; mt++) {
            const int r = wm * 32 + mt * 16 + lr;
#pragma unroll
            for (int half = 0; half < 2; half++) {
                const int m = m0 + r + 8 * half;
                const int b = m >> 6;
                const int s = m & 63;
                const size_t idx = (((size_t)b * NH + h) * NS + s) * HD + d;
                float2 v;
                v.x = acc[mt][nt][2 * half + 0] + b0;
                v.y = acc[mt][nt][2 * half + 1] + b1;
                if (mat == 0) { v.x = f2tf_f(v.x); v.y = f2tf_f(v.y); }
                *(float2*)&dst[idx] = v;
            }
        }
    }
}

// =====================================================================
// Flash cache attention, tf32 legacy mma (proven round-3 kernel).
// =====================================================================
#define KV_LD 68
#define KV_TILE (64 * KV_LD)

__global__ __launch_bounds__(128, 3) void attn_flash(
    const float* __restrict__ mask,
    const float* __restrict__ c0k, const float* __restrict__ c0v,
    const float* __restrict__ c1k, const float* __restrict__ c1v,
    const float* __restrict__ kself, const float* __restrict__ vself,
    float* __restrict__ outctx)
{
    extern __shared__ float sm[];
    float* kbuf   = sm;
    float* vbuf   = kbuf + 2 * KV_TILE;
    float* mask_s = vbuf + 2 * KV_TILE;

    const int bh   = blockIdx.x;
    const int b    = bh / NH;
    const int h    = bh - b * NH;
    const int tid  = threadIdx.x;
    const int lane = tid & 31;
    const int w    = tid >> 5;
    const int lq   = lane & 3;
    const int lr   = lane >> 2;
    const int qb   = lane & 28;

    const float* c0kb = c0k + ((size_t)(b & 7) * NH + h) * L0 * HD;
    const float* c0vb = c0v + ((size_t)(b & 7) * NH + h) * L0 * HD;
    const float* c1kb = c1k + (size_t)bh * L1 * HD;
    const float* c1vb = c1v + (size_t)bh * L1 * HD;
    const float* ksb  = kself + (size_t)bh * NS * HD;
    const float* vsb  = vself + (size_t)bh * NS * HD;

    auto ksrc_of = [&](int c) -> const float* {
        return (c < 6) ? (c0kb + c * 64 * HD)
             : (c < 8) ? (c1kb + (c - 6) * 64 * HD) : ksb;
    };
    auto vsrc_of = [&](int c) -> const float* {
        return (c < 6) ? (c0vb + c * 64 * HD)
             : (c < 8) ? (c1vb + (c - 6) * 64 * HD) : vsb;
    };

    auto load_tile = [&](float* buf, const float* src) {
        const int r  = tid >> 1;
        const int c0 = (tid & 1) * 32;
        float* d = buf + r * KV_LD + c0;
        const float* s = src + r * HD + c0;
#pragma unroll
        for (int i = 0; i < 8; i++) cp16(d + 4 * i, s + 4 * i);
    };

    load_tile(kbuf + KV_TILE, g_q + (size_t)bh * NS * HD);
    cp_commit();
    load_tile(kbuf, ksrc_of(0));
    load_tile(vbuf, vsrc_of(0));
    cp_commit();

    for (int i = tid; i < LTOT; i += 128)
        mask_s[i] = mask[(size_t)b * LTOT + i];

    cp_wait<1>();
    __syncthreads();

    uint32_t qa[8][4];
    {
        const float* qs = kbuf + KV_TILE;
        const int r = w * 16 + lr;
#pragma unroll
        for (int ks = 0; ks < 8; ks++) {
            qa[ks][0] = fu(qs[r * KV_LD + ks * 8 + lq]);
            qa[ks][1] = fu(qs[(r + 8) * KV_LD + ks * 8 + lq]);
            qa[ks][2] = fu(qs[r * KV_LD + ks * 8 + 4 + lq]);
            qa[ks][3] = fu(qs[(r + 8) * KV_LD + ks * 8 + 4 + lq]);
        }
    }
    __syncthreads();

    float m0 = -1e30f, m1 = -1e30f;
    float l0 = 0.f,    l1 = 0.f;
    float o[8][4];
#pragma unroll
    for (int dt = 0; dt < 8; dt++)
#pragma unroll
        for (int i = 0; i < 4; i++) o[dt][i] = 0.f;

    for (int c = 0; c < NCHUNK; c++) {
        if (c < NCHUNK - 1) {
            float* kb = kbuf + ((c + 1) & 1) * KV_TILE;
            float* vb = vbuf + ((c + 1) & 1) * KV_TILE;
            load_tile(kb, ksrc_of(c + 1));
            load_tile(vb, vsrc_of(c + 1));
            cp_commit();
            cp_wait<1>();
        } else {
            cp_wait<0>();
        }
        __syncthreads();

        const float* K = kbuf + (c & 1) * KV_TILE;
        const float* V = vbuf + (c & 1) * KV_TILE;

        float cS[8][4];
#pragma unroll
        for (int nt = 0; nt < 8; nt++)
#pragma unroll
            for (int i = 0; i < 4; i++) cS[nt][i] = 0.f;

#pragma unroll
        for (int ks = 0; ks < 8; ks++) {
#pragma unroll
            for (int nt = 0; nt < 8; nt++) {
                const int n = nt * 8 + lr;
                uint32_t b0 = f2tf(K[n * KV_LD + ks * 8 + lq]);
                uint32_t b1 = f2tf(K[n * KV_LD + ks * 8 + 4 + lq]);
                MMA_TF32(cS[nt], qa[ks], b0, b1);
            }
        }

        float cm0 = -1e30f, cm1 = -1e30f;
#pragma unroll
        for (int nt = 0; nt < 8; nt++) {
            const int col = c * 64 + nt * 8 + 2 * lq;
            const float mv0 = mask_s[col];
            const float mv1 = mask_s[col + 1];
            cS[nt][0] = cS[nt][0] * 0.125f + mv0;
            cS[nt][1] = cS[nt][1] * 0.125f + mv1;
            cS[nt][2] = cS[nt][2] * 0.125f + mv0;
            cS[nt][3] = cS[nt][3] * 0.125f + mv1;
            cm0 = fmaxf(cm0, fmaxf(cS[nt][0], cS[nt][1]));
            cm1 = fmaxf(cm1, fmaxf(cS[nt][2], cS[nt][3]));
        }
#pragma unroll
        for (int off = 1; off <= 2; off <<= 1) {
            cm0 = fmaxf(cm0, __shfl_xor_sync(0xFFFFFFFFu, cm0, off));
            cm1 = fmaxf(cm1, __shfl_xor_sync(0xFFFFFFFFu, cm1, off));
        }

        const float mn0 = fmaxf(m0, cm0);
        const float mn1 = fmaxf(m1, cm1);
        const float a0  = __expf(m0 - mn0);
        const float a1  = __expf(m1 - mn1);
        m0 = mn0; m1 = mn1;

        float s0 = 0.f, s1 = 0.f;
#pragma unroll
        for (int nt = 0; nt < 8; nt++) {
            cS[nt][0] = __expf(cS[nt][0] - mn0);
            cS[nt][1] = __expf(cS[nt][1] - mn0);
            cS[nt][2] = __expf(cS[nt][2] - mn1);
            cS[nt][3] = __expf(cS[nt][3] - mn1);
            s0 += cS[nt][0] + cS[nt][1];
            s1 += cS[nt][2] + cS[nt][3];
        }
#pragma unroll
        for (int off = 1; off <= 2; off <<= 1) {
            s0 += __shfl_xor_sync(0xFFFFFFFFu, s0, off);
            s1 += __shfl_xor_sync(0xFFFFFFFFu, s1, off);
        }
        l0 = l0 * a0 + s0;
        l1 = l1 * a1 + s1;

#pragma unroll
        for (int dt = 0; dt < 8; dt++) {
            o[dt][0] *= a0; o[dt][1] *= a0;
            o[dt][2] *= a1; o[dt][3] *= a1;
        }

#pragma unroll
        for (int kt = 0; kt < 8; kt++) {
            const int sl0 = qb + (lq >> 1);
            const int sl1 = sl0 + 2;
            const bool odd = lq & 1;
            float t00 = __shfl_sync(0xFFFFFFFFu, cS[kt][0], sl0);
            float t10 = __shfl_sync(0xFFFFFFFFu, cS[kt][1], sl0);
            float t01 = __shfl_sync(0xFFFFFFFFu, cS[kt][0], sl1);
            float t11 = __shfl_sync(0xFFFFFFFFu, cS[kt][1], sl1);
            float u00 = __shfl_sync(0xFFFFFFFFu, cS[kt][2], sl0);
            float u10 = __shfl_sync(0xFFFFFFFFu, cS[kt][3], sl0);
            float u01 = __shfl_sync(0xFFFFFFFFu, cS[kt][2], sl1);
            float u11 = __shfl_sync(0xFFFFFFFFu, cS[kt][3], sl1);
            uint32_t pa[4];
            pa[0] = f2tf(odd ? t10 : t00);
            pa[1] = f2tf(odd ? u10 : u00);
            pa[2] = f2tf(odd ? t11 : t01);
            pa[3] = f2tf(odd ? u11 : u01);
#pragma unroll
            for (int dt = 0; dt < 8; dt++) {
                uint32_t b0 = f2tf(V[(kt * 8 + lq) * KV_LD + dt * 8 + lr]);
                uint32_t b1 = f2tf(V[(kt * 8 + 4 + lq) * KV_LD + dt * 8 + lr]);
                MMA_TF32(o[dt], pa, b0, b1);
            }
        }
        __syncthreads();
    }

    {
        const float r0 = 1.f / l0;
        const float r1 = 1.f / l1;
        const int r = w * 16 + lr;
        float* ob0 = outctx + ((size_t)b * NS + r) * NHID + h * HD;
        float* ob1 = outctx + ((size_t)b * NS + r + 8) * NHID + h * HD;
#pragma unroll
        for (int dt = 0; dt < 8; dt++) {
            const int dcol = dt * 8 + 2 * lq;
            float2 v0, v1;
            v0.x = o[dt][0] * r0; v0.y = o[dt][1] * r0;
            v1.x = o[dt][2] * r1; v1.y = o[dt][3] * r1;
            *(float2*)&ob0[dcol] = v0;
            *(float2*)&ob1[dcol] = v1;
        }
    }
}

// =====================================================================
// Host launcher
// =====================================================================
extern "C" void kernel_launch(void* const* d_in, const int* in_sizes, int n_in,
                              void* d_out, int out_size)
{
    const float* hidden = (const float*)d_in[0];
    const float* mask   = (const float*)d_in[1];
    const float* Wq     = (const float*)d_in[2];
    const float* bq     = (const float*)d_in[3];
    const float* Wk     = (const float*)d_in[4];
    const float* bk     = (const float*)d_in[5];
    const float* Wv     = (const float*)d_in[6];
    const float* bv     = (const float*)d_in[7];
    const float* c0k    = (const float*)d_in[8];
    const float* c0v    = (const float*)d_in[9];
    const float* c1k    = (const float*)d_in[10];
    const float* c1v    = (const float*)d_in[11];

    float* out   = (float*)d_out;
    const size_t sect = (size_t)NB * NS * NHID;
    float* out_k = out + sect;
    float* out_v = out + 2 * sect;

    __half *hidh_d, *wh_d;
    cudaGetSymbolAddress((void**)&hidh_d, g_hidh);
    cudaGetSymbolAddress((void**)&wh_d,   g_wh);

    const int gemm_smem = 2 * STAGEW * 4;           // 30720
    const int attn_smem = (4 * KV_TILE + LTOT) * 4; // 71936

    cudaFuncSetAttribute(qkv_gemm_f16,
                         cudaFuncAttributeMaxDynamicSharedMemorySize, gemm_smem);
    cudaFuncSetAttribute(attn_flash,
                         cudaFuncAttributeMaxDynamicSharedMemorySize, attn_smem);

    // convert hidden + weights to fp16 once
    const int nh4 = (NB * NS * NHID) / 4;
    const int nw4 = (NHID * NHID) / 4;
    cvt_f16_kernel<<<2048, 256>>>((const float4*)hidden, (uint2*)hidh_d, nh4);
    cvt_f16_kernel<<<288, 256>>>((const float4*)Wq, (uint2*)(wh_d), nw4);
    cvt_f16_kernel<<<288, 256>>>((const float4*)Wk, (uint2*)(wh_d + (size_t)NHID * NHID), nw4);
    cvt_f16_kernel<<<288, 256>>>((const float4*)Wv, (uint2*)(wh_d + (size_t)2 * NHID * NHID), nw4);

    dim3 ggrid(NB * NS / 128, 3 * NHID / 64);       // (120, 36)
    qkv_gemm_f16<<<ggrid, 256, gemm_smem>>>(bq, bk, bv, out_k, out_v);

    attn_flash<<<NB * NH, 128, attn_smem>>>(mask, c0k, c0v, c1k, c1v,
                                            out_k, out_v, out);
}

// round 9
// speedup vs baseline: 1.7005x; 1.1907x over previous
#include <cuda_runtime.h>
#include <cuda_fp16.h>
#include <cstdint>

// ---------------- problem constants (fixed by the dataset) ----------------
#define NB    240
#define NS    64
#define NHID  768
#define NH    12
#define HD    64
#define L0    384
#define L1    128
#define LTOT  576
#define NCHUNK 9

// device-global scratch (allocation-free)
__device__ __half g_hidh[(size_t)NB * NS * NHID];       // hidden fp16
__device__ __half g_wh  [(size_t)3 * NHID * NHID];      // Wq|Wk|Wv fp16
__device__ __half g_qh  [(size_t)NB * NH * NS * HD];    // q fp16 [bh][s][d]
__device__ __half g_kh  [(size_t)NB * NH * NS * HD];    // k fp16 [bh][s][d]
__device__ __half g_vth [(size_t)NB * NH * NS * HD];    // v fp16 transposed [bh][d][s]
__device__ __half g_c0kh[(size_t)8 * NH * L0 * HD];     // c0 key fp16 [g][j][d]
__device__ __half g_c0vt[(size_t)8 * NH * L0 * HD];     // c0 val fp16 T [g][d][j]
__device__ __half g_c1kh[(size_t)NB * NH * L1 * HD];    // c1 key fp16
__device__ __half g_c1vt[(size_t)NB * NH * L1 * HD];    // c1 val fp16 T

// ---------------- helpers ----------------
__device__ __forceinline__ uint32_t h2u(__half2 h) { return *(uint32_t*)&h; }

#define MMA_F16(c, a, b0, b1)                                               \
    asm volatile(                                                           \
        "mma.sync.aligned.m16n8k16.row.col.f32.f16.f16.f32 "                \
        "{%0,%1,%2,%3}, {%4,%5,%6,%7}, {%8,%9}, {%0,%1,%2,%3};\n"           \
        : "+f"((c)[0]), "+f"((c)[1]), "+f"((c)[2]), "+f"((c)[3])            \
        : "r"((a)[0]), "r"((a)[1]), "r"((a)[2]), "r"((a)[3]),               \
          "r"(b0), "r"(b1))

__device__ __forceinline__ void cp16h(__half* dst, const __half* src) {
    uint32_t d = (uint32_t)__cvta_generic_to_shared(dst);
    asm volatile("cp.async.cg.shared.global [%0], [%1], 16;\n" :: "r"(d), "l"(src));
}
__device__ __forceinline__ void cp16f(float* dst, const float* src) {
    uint32_t d = (uint32_t)__cvta_generic_to_shared(dst);
    asm volatile("cp.async.cg.shared.global [%0], [%1], 16;\n" :: "r"(d), "l"(src));
}
__device__ __forceinline__ void cp_commit() {
    asm volatile("cp.async.commit_group;\n");
}
template <int N> __device__ __forceinline__ void cp_wait() {
    asm volatile("cp.async.wait_group %0;\n" :: "n"(N));
}

// =====================================================================
// float -> fp16 elementwise convert (float4 in, 8B out)
// =====================================================================
__global__ __launch_bounds__(256) void cvt_f16_kernel(
    const float4* __restrict__ src, uint2* __restrict__ dst, int n4)
{
    int i = blockIdx.x * blockDim.x + threadIdx.x;
    const int stride = gridDim.x * blockDim.x;
    for (; i < n4; i += stride) {
        float4 v = src[i];
        __half2 lo = __floats2half2_rn(v.x, v.y);
        __half2 hi = __floats2half2_rn(v.z, v.w);
        uint2 o;
        o.x = h2u(lo);
        o.y = h2u(hi);
        dst[i] = o;
    }
}

// =====================================================================
// fp32 [G][R][64] -> fp16 transposed [G][64][R]; block per 64x64 tile.
// =====================================================================
__global__ __launch_bounds__(256) void transpose_f16_kernel(
    const float* __restrict__ src, __half* __restrict__ dst, int R)
{
    __shared__ float t[64][65];
    const int g  = blockIdx.y;
    const int r0 = blockIdx.x * 64;
    const int tid = threadIdx.x;

    const float* s = src + ((size_t)g * R + r0) * 64;
    for (int i = tid; i < 4096; i += 256) {
        const int r = i >> 6, d = i & 63;
        t[r][d] = s[r * 64 + d];
    }
    __syncthreads();
    __half* o = dst + (size_t)g * 64 * R + r0;
    for (int i = tid; i < 4096; i += 256) {
        const int d = i >> 6, r = i & 63;
        o[(size_t)d * R + r] = __float2half(t[r][d]);
    }
}

// =====================================================================
// QKV projection, fp16 mma (round-8 proven kernel); epilogue now also
// emits fp16 q/k and TRANSPOSED fp16 v for the fp16 attention.
// =====================================================================
#define GLDW  20
#define A_W   (128 * GLDW)
#define B_W   (64 * GLDW)
#define STAGEW (A_W + B_W)

__global__ __launch_bounds__(256) void qkv_gemm_f16(
    const float* __restrict__ bq, const float* __restrict__ bk_,
    const float* __restrict__ bv,
    float* __restrict__ out_k, float* __restrict__ out_v)
{
    extern __shared__ uint32_t smw[];

    const int m0  = blockIdx.x * 128;
    const int n0g = blockIdx.y * 64;
    const int mat = n0g / NHID;
    const int n0  = n0g - mat * NHID;

    const __half* Ag = g_hidh;
    const __half* Bg = g_wh + (size_t)mat * NHID * NHID;
    const float*  bi = (mat == 0) ? bq : (mat == 1) ? bk_ : bv;

    const int tid  = threadIdx.x;
    const int lane = tid & 31;
    const int w    = tid >> 5;
    const int wm   = w & 3;
    const int wn   = w >> 2;
    const int lq   = lane & 3;
    const int lr   = lane >> 2;

    const int arow = tid >> 2;
    const int acu  = tid & 3;

    uint4 ra[2], rb;

    auto ldglob = [&](int k0) {
        ra[0] = *(const uint4*)(Ag + (size_t)(m0 + arow) * NHID + k0 + acu * 8);
        ra[1] = *(const uint4*)(Ag + (size_t)(m0 + arow + 64) * NHID + k0 + acu * 8);
        rb    = *(const uint4*)(Bg + (size_t)(n0 + arow) * NHID + k0 + acu * 8);
    };
    auto st_smem = [&](int buf) {
        uint32_t* A = smw + buf * STAGEW;
        uint32_t* B = A + A_W;
        *(uint4*)(A + arow * GLDW + acu * 4)        = ra[0];
        *(uint4*)(A + (arow + 64) * GLDW + acu * 4) = ra[1];
        *(uint4*)(B + arow * GLDW + acu * 4)        = rb;
    };

    float acc[2][4][4];
#pragma unroll
    for (int mt = 0; mt < 2; mt++)
#pragma unroll
        for (int nt = 0; nt < 4; nt++)
#pragma unroll
            for (int i = 0; i < 4; i++) acc[mt][nt][i] = 0.f;

    auto compute = [&](int buf) {
        const uint32_t* A = smw + buf * STAGEW;
        const uint32_t* B = A + A_W;
#pragma unroll
        for (int ks = 0; ks < 2; ks++) {
            const int kw = ks * 8;
            uint32_t af[2][4];
#pragma unroll
            for (int mt = 0; mt < 2; mt++) {
                const int r = wm * 32 + mt * 16 + lr;
                af[mt][0] = A[r * GLDW + kw + lq];
                af[mt][1] = A[(r + 8) * GLDW + kw + lq];
                af[mt][2] = A[r * GLDW + kw + 4 + lq];
                af[mt][3] = A[(r + 8) * GLDW + kw + 4 + lq];
            }
            uint32_t bf[4][2];
#pragma unroll
            for (int nt = 0; nt < 4; nt++) {
                const int n = wn * 32 + nt * 8 + lr;
                bf[nt][0] = B[n * GLDW + kw + lq];
                bf[nt][1] = B[n * GLDW + kw + 4 + lq];
            }
#pragma unroll
            for (int mt = 0; mt < 2; mt++)
#pragma unroll
                for (int nt = 0; nt < 4; nt++)
                    MMA_F16(acc[mt][nt], af[mt], bf[nt][0], bf[nt][1]);
        }
    };

    ldglob(0);
    st_smem(0);
    __syncthreads();

    for (int it = 0; it < 24; it++) {
        if (it < 23) ldglob((it + 1) * 32);
        compute(it & 1);
        if (it < 23) st_smem((it + 1) & 1);
        __syncthreads();
    }

    // epilogue: bias + scatter
#pragma unroll
    for (int nt = 0; nt < 4; nt++) {
        const int ncol = n0 + wn * 32 + nt * 8 + 2 * lq;
        const float b0 = bi[ncol];
        const float b1 = bi[ncol + 1];
        const int h = ncol >> 6;
        const int d = ncol & 63;
#pragma unroll
        for (int mt = 0; mt < 2; mt++) {
            const int r = wm * 32 + mt * 16 + lr;
#pragma unroll
            for (int half = 0; half < 2; half++) {
                const int m = m0 + r + 8 * half;
                const int b = m >> 6;
                const int s = m & 63;
                const size_t bh = (size_t)b * NH + h;
                float2 v;
                v.x = acc[mt][nt][2 * half + 0] + b0;
                v.y = acc[mt][nt][2 * half + 1] + b1;
                if (mat == 0) {
                    *(__half2*)&g_qh[(bh * 64 + s) * 64 + d] =
                        __floats2half2_rn(v.x, v.y);
                } else if (mat == 1) {
                    *(float2*)&out_k[(bh * 64 + s) * 64 + d] = v;
                    *(__half2*)&g_kh[(bh * 64 + s) * 64 + d] =
                        __floats2half2_rn(v.x, v.y);
                } else {
                    *(float2*)&out_v[(bh * 64 + s) * 64 + d] = v;
                    g_vth[(bh * 64 + d) * 64 + s]     = __float2half(v.x);
                    g_vth[(bh * 64 + d + 1) * 64 + s] = __float2half(v.y);
                }
            }
        }
    }
}

// =====================================================================
// Flash cache attention, all-fp16 mma (m16n8k16).
// K tiles [j][d] fp16, V tiles pre-transposed [d][j] fp16; smem row
// stride 72 halves (36 words, ≡4 mod 32 -> conflict-free).
// P: C-frag cols (2lq,2lq+1) of tile 2kt ARE A-frag a0 of k-block kt
// -> pack in-thread, no shuffles.
// =====================================================================
#define KVH_LD 72
#define KVH_TILE (64 * KVH_LD)

__global__ __launch_bounds__(128, 3) void attn_flash_f16(
    const float* __restrict__ mask,
    float* __restrict__ outctx)
{
    extern __shared__ __half smh[];
    __half* kbuf   = smh;                       // [2][64][72]
    __half* vbuf   = kbuf + 2 * KVH_TILE;       // [2][64][72]
    float*  mask_s = (float*)(vbuf + 2 * KVH_TILE);   // [576]

    const int bh   = blockIdx.x;
    const int b    = bh / NH;
    const int h    = bh - b * NH;
    const int tid  = threadIdx.x;
    const int lane = tid & 31;
    const int w    = tid >> 5;
    const int lq   = lane & 3;
    const int lr   = lane >> 2;

    const __half* c0kb = g_c0kh + ((size_t)(b & 7) * NH + h) * L0 * HD;
    const __half* c0vb = g_c0vt + ((size_t)(b & 7) * NH + h) * HD * L0;  // [d][384]
    const __half* c1kb = g_c1kh + (size_t)bh * L1 * HD;
    const __half* c1vb = g_c1vt + (size_t)bh * HD * L1;                  // [d][128]
    const __half* ksb  = g_kh  + (size_t)bh * NS * HD;
    const __half* vsb  = g_vth + (size_t)bh * HD * NS;                   // [d][64]

    // K sources: all row stride 64 ([j][d])
    auto ksrc_of = [&](int c) -> const __half* {
        return (c < 6) ? (c0kb + c * 64 * HD)
             : (c < 8) ? (c1kb + (c - 6) * 64 * HD) : ksb;
    };
    // Vt sources: row d, stride varies; col offset = chunk base j
    auto vsrc_of = [&](int c, int& vstride) -> const __half* {
        if (c < 6)  { vstride = L0; return c0vb + c * 64; }
        if (c < 8)  { vstride = L1; return c1vb + (c - 6) * 64; }
        vstride = NS; return vsb;
    };

    // 64x64 half tile -> smem stride 72; 128 thr x 64B
    auto load_tile = [&](__half* buf, const __half* src, int sstride) {
        const int r  = tid >> 1;
        const int c0 = (tid & 1) * 32;
        __half* d = buf + r * KVH_LD + c0;
        const __half* s = src + (size_t)r * sstride + c0;
#pragma unroll
        for (int i = 0; i < 4; i++) cp16h(d + 8 * i, s + 8 * i);
    };

    // prologue: Q -> kbuf[1]; chunk0 -> buf0; mask
    load_tile(kbuf + KVH_TILE, g_qh + (size_t)bh * NS * HD, HD);
    cp_commit();
    {
        int vs;
        const __half* vsrc = vsrc_of(0, vs);
        load_tile(kbuf, ksrc_of(0), HD);
        load_tile(vbuf, vsrc, vs);
        cp_commit();
    }

    {
        const int r  = tid >> 1;
        const int c0 = (tid & 1) * 32;
        // mask via cp.async too (576 floats): rows of 128 threads
        for (int i = tid * 4; i < LTOT; i += 128 * 4)
            cp16f(mask_s + i, mask + (size_t)b * LTOT + i);
        cp_commit();
        (void)r; (void)c0;
    }

    cp_wait<2>();   // Q group done (mask+chunk0 still possibly in flight)
    __syncthreads();

    // Q fragments: 4 k16-steps x 4 regs
    uint32_t qa[4][4];
    {
        const uint32_t* Qw = (const uint32_t*)(kbuf + KVH_TILE);
        const int r = w * 16 + lr;
#pragma unroll
        for (int ks = 0; ks < 4; ks++) {
            qa[ks][0] = Qw[r * 36 + ks * 8 + lq];
            qa[ks][1] = Qw[(r + 8) * 36 + ks * 8 + lq];
            qa[ks][2] = Qw[r * 36 + ks * 8 + 4 + lq];
            qa[ks][3] = Qw[(r + 8) * 36 + ks * 8 + 4 + lq];
        }
    }
    __syncthreads();   // Q reads done before chunk1 overwrites kbuf[1]

    float m0 = -1e30f, m1 = -1e30f;
    float l0 = 0.f,    l1 = 0.f;
    float o[8][4];
#pragma unroll
    for (int dt = 0; dt < 8; dt++)
#pragma unroll
        for (int i = 0; i < 4; i++) o[dt][i] = 0.f;

    for (int c = 0; c < NCHUNK; c++) {
        if (c < NCHUNK - 1) {
            int vs;
            const __half* vsrc = vsrc_of(c + 1, vs);
            load_tile(kbuf + ((c + 1) & 1) * KVH_TILE, ksrc_of(c + 1), HD);
            load_tile(vbuf + ((c + 1) & 1) * KVH_TILE, vsrc, vs);
            cp_commit();
            cp_wait<1>();
        } else {
            cp_wait<0>();
        }
        __syncthreads();

        const uint32_t* K  = (const uint32_t*)(kbuf + (c & 1) * KVH_TILE);
        const uint32_t* Vt = (const uint32_t*)(vbuf + (c & 1) * KVH_TILE);

        // ---- S = Q K^T ----
        float cS[8][4];
#pragma unroll
        for (int nt = 0; nt < 8; nt++)
#pragma unroll
            for (int i = 0; i < 4; i++) cS[nt][i] = 0.f;

#pragma unroll
        for (int ks = 0; ks < 4; ks++) {
#pragma unroll
            for (int nt = 0; nt < 8; nt++) {
                const int n = nt * 8 + lr;
                uint32_t b0 = K[n * 36 + ks * 8 + lq];
                uint32_t b1 = K[n * 36 + ks * 8 + 4 + lq];
                MMA_F16(cS[nt], qa[ks], b0, b1);
            }
        }

        // ---- mask + scale + chunk row max ----
        float cm0 = -1e30f, cm1 = -1e30f;
#pragma unroll
        for (int nt = 0; nt < 8; nt++) {
            const int col = c * 64 + nt * 8 + 2 * lq;
            const float mv0 = mask_s[col];
            const float mv1 = mask_s[col + 1];
            cS[nt][0] = cS[nt][0] * 0.125f + mv0;
            cS[nt][1] = cS[nt][1] * 0.125f + mv1;
            cS[nt][2] = cS[nt][2] * 0.125f + mv0;
            cS[nt][3] = cS[nt][3] * 0.125f + mv1;
            cm0 = fmaxf(cm0, fmaxf(cS[nt][0], cS[nt][1]));
            cm1 = fmaxf(cm1, fmaxf(cS[nt][2], cS[nt][3]));
        }
#pragma unroll
        for (int off = 1; off <= 2; off <<= 1) {
            cm0 = fmaxf(cm0, __shfl_xor_sync(0xFFFFFFFFu, cm0, off));
            cm1 = fmaxf(cm1, __shfl_xor_sync(0xFFFFFFFFu, cm1, off));
        }

        const float mn0 = fmaxf(m0, cm0);
        const float mn1 = fmaxf(m1, cm1);
        const float a0  = __expf(m0 - mn0);
        const float a1  = __expf(m1 - mn1);
        m0 = mn0; m1 = mn1;

        float s0 = 0.f, s1 = 0.f;
#pragma unroll
        for (int nt = 0; nt < 8; nt++) {
            cS[nt][0] = __expf(cS[nt][0] - mn0);
            cS[nt][1] = __expf(cS[nt][1] - mn0);
            cS[nt][2] = __expf(cS[nt][2] - mn1);
            cS[nt][3] = __expf(cS[nt][3] - mn1);
            s0 += cS[nt][0] + cS[nt][1];
            s1 += cS[nt][2] + cS[nt][3];
        }
#pragma unroll
        for (int off = 1; off <= 2; off <<= 1) {
            s0 += __shfl_xor_sync(0xFFFFFFFFu, s0, off);
            s1 += __shfl_xor_sync(0xFFFFFFFFu, s1, off);
        }
        l0 = l0 * a0 + s0;
        l1 = l1 * a1 + s1;

#pragma unroll
        for (int dt = 0; dt < 8; dt++) {
            o[dt][0] *= a0; o[dt][1] *= a0;
            o[dt][2] *= a1; o[dt][3] *= a1;
        }

        // ---- PV: in-thread P pack (C tiles 2kt,2kt+1 -> A frag kt) ----
#pragma unroll
        for (int kt = 0; kt < 4; kt++) {
            uint32_t pa[4];
            pa[0] = h2u(__floats2half2_rn(cS[2 * kt][0],     cS[2 * kt][1]));
            pa[1] = h2u(__floats2half2_rn(cS[2 * kt][2],     cS[2 * kt][3]));
            pa[2] = h2u(__floats2half2_rn(cS[2 * kt + 1][0], cS[2 * kt + 1][1]));
            pa[3] = h2u(__floats2half2_rn(cS[2 * kt + 1][2], cS[2 * kt + 1][3]));
#pragma unroll
            for (int dt = 0; dt < 8; dt++) {
                const int n = dt * 8 + lr;
                uint32_t b0 = Vt[n * 36 + kt * 8 + lq];
                uint32_t b1 = Vt[n * 36 + kt * 8 + 4 + lq];
                MMA_F16(o[dt], pa, b0, b1);
            }
        }
        __syncthreads();
    }

    // epilogue: normalize + write out[b, s, h*64 + d]
    {
        const float r0 = 1.f / l0;
        const float r1 = 1.f / l1;
        const int r = w * 16 + lr;
        float* ob0 = outctx + ((size_t)b * NS + r) * NHID + h * HD;
        float* ob1 = outctx + ((size_t)b * NS + r + 8) * NHID + h * HD;
#pragma unroll
        for (int dt = 0; dt < 8; dt++) {
            const int dcol = dt * 8 + 2 * lq;
            float2 v0, v1;
            v0.x = o[dt][0] * r0; v0.y = o[dt][1] * r0;
            v1.x = o[dt][2] * r1; v1.y = o[dt][3] * r1;
            *(float2*)&ob0[dcol] = v0;
            *(float2*)&ob1[dcol] = v1;
        }
    }
}

// =====================================================================
// Host launcher
// =====================================================================
extern "C" void kernel_launch(void* const* d_in, const int* in_sizes, int n_in,
                              void* d_out, int out_size)
{
    const float* hidden = (const float*)d_in[0];
    const float* mask   = (const float*)d_in[1];
    const float* Wq     = (const float*)d_in[2];
    const float* bq     = (const float*)d_in[3];
    const float* Wk     = (const float*)d_in[4];
    const float* bk     = (const float*)d_in[5];
    const float* Wv     = (const float*)d_in[6];
    const float* bv     = (const float*)d_in[7];
    const float* c0k    = (const float*)d_in[8];
    const float* c0v    = (const float*)d_in[9];
    const float* c1k    = (const float*)d_in[10];
    const float* c1v    = (const float*)d_in[11];

    float* out   = (float*)d_out;
    const size_t sect = (size_t)NB * NS * NHID;
    float* out_k = out + sect;
    float* out_v = out + 2 * sect;

    __half *hidh_d, *wh_d, *c0kh_d, *c0vt_d, *c1kh_d, *c1vt_d;
    cudaGetSymbolAddress((void**)&hidh_d, g_hidh);
    cudaGetSymbolAddress((void**)&wh_d,   g_wh);
    cudaGetSymbolAddress((void**)&c0kh_d, g_c0kh);
    cudaGetSymbolAddress((void**)&c0vt_d, g_c0vt);
    cudaGetSymbolAddress((void**)&c1kh_d, g_c1kh);
    cudaGetSymbolAddress((void**)&c1vt_d, g_c1vt);

    const int gemm_smem = 2 * STAGEW * 4;                 // 30720
    const int attn_smem = 4 * KVH_TILE * 2 + LTOT * 4;    // 39168

    cudaFuncSetAttribute(qkv_gemm_f16,
                         cudaFuncAttributeMaxDynamicSharedMemorySize, gemm_smem);
    cudaFuncSetAttribute(attn_flash_f16,
                         cudaFuncAttributeMaxDynamicSharedMemorySize, attn_smem);

    // preprocessing: fp16 converts + V transposes
    const int nh4  = (NB * NS * NHID) / 4;
    const int nw4  = (NHID * NHID) / 4;
    const int nc04 = (8 * NH * L0 * HD) / 4;       // 589824
    const int nc14 = (NB * NH * L1 * HD) / 4;      // 5898240
    cvt_f16_kernel<<<2048, 256>>>((const float4*)hidden, (uint2*)hidh_d, nh4);
    cvt_f16_kernel<<<288, 256>>>((const float4*)Wq, (uint2*)(wh_d), nw4);
    cvt_f16_kernel<<<288, 256>>>((const float4*)Wk, (uint2*)(wh_d + (size_t)NHID * NHID), nw4);
    cvt_f16_kernel<<<288, 256>>>((const float4*)Wv, (uint2*)(wh_d + (size_t)2 * NHID * NHID), nw4);
    cvt_f16_kernel<<<1024, 256>>>((const float4*)c0k, (uint2*)c0kh_d, nc04);
    cvt_f16_kernel<<<4096, 256>>>((const float4*)c1k, (uint2*)c1kh_d, nc14);
    {
        dim3 g0(L0 / 64, 8 * NH);       // (6, 96)
        transpose_f16_kernel<<<g0, 256>>>(c0v, c0vt_d, L0);
        dim3 g1(L1 / 64, NB * NH);      // (2, 2880)
        transpose_f16_kernel<<<g1, 256>>>(c1v, c1vt_d, L1);
    }

    dim3 ggrid(NB * NS / 128, 3 * NHID / 64);       // (120, 36)
    qkv_gemm_f16<<<ggrid, 256, gemm_smem>>>(bq, bk, bv, out_k, out_v);

    attn_flash_f16<<<NB * NH, 128, attn_smem>>>(mask, out);
}

// round 10
// speedup vs baseline: 1.7787x; 1.0460x over previous
#include <cuda_runtime.h>
#include <cuda_fp16.h>
#include <cstdint>

// ---------------- problem constants (fixed by the dataset) ----------------
#define NB    240
#define NS    64
#define NHID  768
#define NH    12
#define HD    64
#define L0    384
#define L1    128
#define LTOT  576
#define NCHUNK 9

// device-global scratch (allocation-free)
__device__ __half g_hidh[(size_t)NB * NS * NHID];       // hidden fp16
__device__ __half g_wh  [(size_t)3 * NHID * NHID];      // Wq|Wk|Wv fp16
__device__ __half g_qh  [(size_t)NB * NH * NS * HD];    // q fp16 [bh][s][d]
__device__ __half g_kh  [(size_t)NB * NH * NS * HD];    // k fp16 [bh][s][d]
__device__ __half g_vth [(size_t)NB * NH * NS * HD];    // v fp16 T [bh][d][s]
__device__ __half g_c0kh[(size_t)8 * NH * L0 * HD];     // c0 key fp16 [g][j][d]
__device__ __half g_c0vt[(size_t)8 * NH * L0 * HD];     // c0 val fp16 T [g][d][j]
__device__ __half g_c1kh[(size_t)NB * NH * L1 * HD];    // c1 key fp16
__device__ __half g_c1vt[(size_t)NB * NH * L1 * HD];    // c1 val fp16 T

// ---------------- helpers ----------------
__device__ __forceinline__ uint32_t h2u(__half2 h) { return *(uint32_t*)&h; }

__device__ __forceinline__ uint32_t smem_u32(const void* p) {
    uint32_t a;
    asm("{ .reg .u64 t; cvta.to.shared.u64 t, %1; cvt.u32.u64 %0, t; }"
        : "=r"(a) : "l"(p));
    return a;
}

#define MMA_F16(c, a, b0, b1)                                               \
    asm volatile(                                                           \
        "mma.sync.aligned.m16n8k16.row.col.f32.f16.f16.f32 "                \
        "{%0,%1,%2,%3}, {%4,%5,%6,%7}, {%8,%9}, {%0,%1,%2,%3};\n"           \
        : "+f"((c)[0]), "+f"((c)[1]), "+f"((c)[2]), "+f"((c)[3])            \
        : "r"((a)[0]), "r"((a)[1]), "r"((a)[2]), "r"((a)[3]),               \
          "r"(b0), "r"(b1))

__device__ __forceinline__ void ldm_x4(uint32_t& r0, uint32_t& r1,
                                       uint32_t& r2, uint32_t& r3,
                                       uint32_t addr) {
    asm volatile("ldmatrix.sync.aligned.m8n8.x4.shared.b16 {%0,%1,%2,%3}, [%4];"
                 : "=r"(r0), "=r"(r1), "=r"(r2), "=r"(r3) : "r"(addr));
}

__device__ __forceinline__ void cp16h(__half* dst, const __half* src) {
    uint32_t d = (uint32_t)__cvta_generic_to_shared(dst);
    asm volatile("cp.async.cg.shared.global [%0], [%1], 16;\n" :: "r"(d), "l"(src));
}
__device__ __forceinline__ void cp16f(float* dst, const float* src) {
    uint32_t d = (uint32_t)__cvta_generic_to_shared(dst);
    asm volatile("cp.async.cg.shared.global [%0], [%1], 16;\n" :: "r"(d), "l"(src));
}
__device__ __forceinline__ void cp_commit() {
    asm volatile("cp.async.commit_group;\n");
}
template <int N> __device__ __forceinline__ void cp_wait() {
    asm volatile("cp.async.wait_group %0;\n" :: "n"(N));
}

// =====================================================================
// float -> fp16 elementwise convert
// =====================================================================
__global__ __launch_bounds__(256) void cvt_f16_kernel(
    const float4* __restrict__ src, uint2* __restrict__ dst, int n4)
{
    int i = blockIdx.x * blockDim.x + threadIdx.x;
    const int stride = gridDim.x * blockDim.x;
    for (; i < n4; i += stride) {
        float4 v = src[i];
        __half2 lo = __floats2half2_rn(v.x, v.y);
        __half2 hi = __floats2half2_rn(v.z, v.w);
        uint2 o;
        o.x = h2u(lo);
        o.y = h2u(hi);
        dst[i] = o;
    }
}

// =====================================================================
// fp32 [G][R][64] -> fp16 transposed [G][64][R]
// =====================================================================
__global__ __launch_bounds__(256) void transpose_f16_kernel(
    const float* __restrict__ src, __half* __restrict__ dst, int R)
{
    __shared__ float t[64][65];
    const int g  = blockIdx.y;
    const int r0 = blockIdx.x * 64;
    const int tid = threadIdx.x;

    const float* s = src + ((size_t)g * R + r0) * 64;
    for (int i = tid; i < 4096; i += 256) {
        const int r = i >> 6, d = i & 63;
        t[r][d] = s[r * 64 + d];
    }
    __syncthreads();
    __half* o = dst + (size_t)g * 64 * R + r0;
    for (int i = tid; i < 4096; i += 256) {
        const int d = i >> 6, r = i & 63;
        o[(size_t)d * R + r] = __float2half(t[r][d]);
    }
}

// =====================================================================
// QKV projection, fp16 mma + ldmatrix operand delivery.
// Block 128x64, BK=32, 8 warps (4x2), warp tile 32x32. Row 40 halves
// (80 B) -> ldmatrix conflict-free (banks {0,20,8,28,16,4,24,12}).
// =====================================================================
#define GLDW  20
#define A_W   (128 * GLDW)
#define B_W   (64 * GLDW)
#define STAGEW (A_W + B_W)
#define ROWB  80                       // bytes per smem row

__global__ __launch_bounds__(256) void qkv_gemm_f16(
    const float* __restrict__ bq, const float* __restrict__ bk_,
    const float* __restrict__ bv,
    float* __restrict__ out_k, float* __restrict__ out_v)
{
    extern __shared__ uint32_t smw[];
    const uint32_t smem_b = smem_u32(smw);

    const int m0  = blockIdx.x * 128;
    const int n0g = blockIdx.y * 64;
    const int mat = n0g / NHID;
    const int n0  = n0g - mat * NHID;

    const __half* Ag = g_hidh;
    const __half* Bg = g_wh + (size_t)mat * NHID * NHID;
    const float*  bi = (mat == 0) ? bq : (mat == 1) ? bk_ : bv;

    const int tid  = threadIdx.x;
    const int lane = tid & 31;
    const int w    = tid >> 5;
    const int wm   = w & 3;
    const int wn   = w >> 2;
    const int lq   = lane & 3;
    const int lr   = lane >> 2;

    // ldmatrix per-lane addressing
    const int lg = lane >> 3, lrs = lane & 7;
    const int a_radd = (lg & 1) * 8 + lrs;     // A: row within 16-tile
    const int a_kadd = (lg >> 1) * 8;          // A: k-half offset (halves)
    const int b_radd = (lg >> 1) * 8 + lrs;    // B: row within 16-group
    const int b_kadd = (lg & 1) * 8;           // B: k-half offset

    const int arow = tid >> 2;
    const int acu  = tid & 3;

    uint4 ra[2], rb;

    auto ldglob = [&](int k0) {
        ra[0] = *(const uint4*)(Ag + (size_t)(m0 + arow) * NHID + k0 + acu * 8);
        ra[1] = *(const uint4*)(Ag + (size_t)(m0 + arow + 64) * NHID + k0 + acu * 8);
        rb    = *(const uint4*)(Bg + (size_t)(n0 + arow) * NHID + k0 + acu * 8);
    };
    auto st_smem = [&](int buf) {
        uint32_t* A = smw + buf * STAGEW;
        uint32_t* B = A + A_W;
        *(uint4*)(A + arow * GLDW + acu * 4)        = ra[0];
        *(uint4*)(A + (arow + 64) * GLDW + acu * 4) = ra[1];
        *(uint4*)(B + arow * GLDW + acu * 4)        = rb;
    };

    float acc[2][4][4];
#pragma unroll
    for (int mt = 0; mt < 2; mt++)
#pragma unroll
        for (int nt = 0; nt < 4; nt++)
#pragma unroll
            for (int i = 0; i < 4; i++) acc[mt][nt][i] = 0.f;

    auto compute = [&](int buf) {
        const uint32_t Ab = smem_b + buf * STAGEW * 4;
        const uint32_t Bb = Ab + A_W * 4;
#pragma unroll
        for (int ks = 0; ks < 2; ks++) {
            uint32_t af[2][4];
#pragma unroll
            for (int mt = 0; mt < 2; mt++) {
                const uint32_t addr = Ab
                    + (uint32_t)((wm * 32 + mt * 16 + a_radd) * ROWB
                                 + (ks * 16 + a_kadd) * 2);
                ldm_x4(af[mt][0], af[mt][1], af[mt][2], af[mt][3], addr);
            }
            uint32_t bf[4][2];
#pragma unroll
            for (int np = 0; np < 2; np++) {
                const uint32_t addr = Bb
                    + (uint32_t)((wn * 32 + np * 16 + b_radd) * ROWB
                                 + (ks * 16 + b_kadd) * 2);
                ldm_x4(bf[2 * np][0], bf[2 * np][1],
                       bf[2 * np + 1][0], bf[2 * np + 1][1], addr);
            }
#pragma unroll
            for (int mt = 0; mt < 2; mt++)
#pragma unroll
                for (int nt = 0; nt < 4; nt++)
                    MMA_F16(acc[mt][nt], af[mt], bf[nt][0], bf[nt][1]);
        }
    };

    ldglob(0);
    st_smem(0);
    __syncthreads();

    for (int it = 0; it < 24; it++) {
        if (it < 23) ldglob((it + 1) * 32);
        compute(it & 1);
        if (it < 23) st_smem((it + 1) & 1);
        __syncthreads();
    }

    // epilogue: bias + scatter (fp32 k/v outputs + fp16 q/k + fp16 v^T)
#pragma unroll
    for (int nt = 0; nt < 4; nt++) {
        const int ncol = n0 + wn * 32 + nt * 8 + 2 * lq;
        const float b0 = bi[ncol];
        const float b1 = bi[ncol + 1];
        const int h = ncol >> 6;
        const int d = ncol & 63;
#pragma unroll
        for (int mt = 0; mt < 2; mt++) {
            const int r = wm * 32 + mt * 16 + lr;
#pragma unroll
            for (int half = 0; half < 2; half++) {
                const int m = m0 + r + 8 * half;
                const int b = m >> 6;
                const int s = m & 63;
                const size_t bh = (size_t)b * NH + h;
                float2 v;
                v.x = acc[mt][nt][2 * half + 0] + b0;
                v.y = acc[mt][nt][2 * half + 1] + b1;
                if (mat == 0) {
                    *(__half2*)&g_qh[(bh * 64 + s) * 64 + d] =
                        __floats2half2_rn(v.x, v.y);
                } else if (mat == 1) {
                    *(float2*)&out_k[(bh * 64 + s) * 64 + d] = v;
                    *(__half2*)&g_kh[(bh * 64 + s) * 64 + d] =
                        __floats2half2_rn(v.x, v.y);
                } else {
                    *(float2*)&out_v[(bh * 64 + s) * 64 + d] = v;
                    g_vth[(bh * 64 + d) * 64 + s]     = __float2half(v.x);
                    g_vth[(bh * 64 + d + 1) * 64 + s] = __float2half(v.y);
                }
            }
        }
    }
}

// =====================================================================
// Flash cache attention, fp16 mma + ldmatrix. Row stride 72 halves
// (144 B) -> ldmatrix conflict-free (16B chunks 0..112 mod 128).
// =====================================================================
#define KVH_LD 72
#define KVH_TILE (64 * KVH_LD)
#define KROWB 144

__global__ __launch_bounds__(128, 3) void attn_flash_f16(
    const float* __restrict__ mask,
    float* __restrict__ outctx)
{
    extern __shared__ __half smh[];
    __half* kbuf   = smh;                       // [2][64][72]
    __half* vbuf   = kbuf + 2 * KVH_TILE;       // [2][64][72]
    float*  mask_s = (float*)(vbuf + 2 * KVH_TILE);   // [576]
    const uint32_t kb_b = smem_u32(kbuf);
    const uint32_t vb_b = smem_u32(vbuf);

    const int bh   = blockIdx.x;
    const int b    = bh / NH;
    const int h    = bh - b * NH;
    const int tid  = threadIdx.x;
    const int lane = tid & 31;
    const int w    = tid >> 5;
    const int lq   = lane & 3;
    const int lr   = lane >> 2;

    // ldmatrix per-lane addressing (B-operand shape)
    const int lg = lane >> 3, lrs = lane & 7;
    const int b_radd = (lg >> 1) * 8 + lrs;
    const int b_kadd = (lg & 1) * 8;

    const __half* c0kb = g_c0kh + ((size_t)(b & 7) * NH + h) * L0 * HD;
    const __half* c0vb = g_c0vt + ((size_t)(b & 7) * NH + h) * HD * L0;
    const __half* c1kb = g_c1kh + (size_t)bh * L1 * HD;
    const __half* c1vb = g_c1vt + (size_t)bh * HD * L1;
    const __half* ksb  = g_kh  + (size_t)bh * NS * HD;
    const __half* vsb  = g_vth + (size_t)bh * HD * NS;

    auto ksrc_of = [&](int c) -> const __half* {
        return (c < 6) ? (c0kb + c * 64 * HD)
             : (c < 8) ? (c1kb + (c - 6) * 64 * HD) : ksb;
    };
    auto vsrc_of = [&](int c, int& vstride) -> const __half* {
        if (c < 6)  { vstride = L0; return c0vb + c * 64; }
        if (c < 8)  { vstride = L1; return c1vb + (c - 6) * 64; }
        vstride = NS; return vsb;
    };

    auto load_tile = [&](__half* buf, const __half* src, int sstride) {
        const int r  = tid >> 1;
        const int c0 = (tid & 1) * 32;
        __half* d = buf + r * KVH_LD + c0;
        const __half* s = src + (size_t)r * sstride + c0;
#pragma unroll
        for (int i = 0; i < 4; i++) cp16h(d + 8 * i, s + 8 * i);
    };

    // prologue: Q -> kbuf[1]; chunk0 -> buf0; mask
    load_tile(kbuf + KVH_TILE, g_qh + (size_t)bh * NS * HD, HD);
    cp_commit();
    {
        int vs;
        const __half* vsrc = vsrc_of(0, vs);
        load_tile(kbuf, ksrc_of(0), HD);
        load_tile(vbuf, vsrc, vs);
        cp_commit();
    }
    for (int i = tid * 4; i < LTOT; i += 128 * 4)
        cp16f(mask_s + i, mask + (size_t)b * LTOT + i);
    cp_commit();

    cp_wait<2>();
    __syncthreads();

    // Q fragments via ldmatrix (A-operand shape): rows w*16.., 4 k-steps
    uint32_t qa[4][4];
    {
        const int a_radd = (lg & 1) * 8 + lrs;
        const int a_kadd = (lg >> 1) * 8;
        const uint32_t Qb = kb_b + KVH_TILE * 2;   // bytes
#pragma unroll
        for (int ks = 0; ks < 4; ks++) {
            const uint32_t addr = Qb
                + (uint32_t)((w * 16 + a_radd) * KROWB + (ks * 16 + a_kadd) * 2);
            ldm_x4(qa[ks][0], qa[ks][1], qa[ks][2], qa[ks][3], addr);
        }
    }
    __syncthreads();

    float m0 = -1e30f, m1 = -1e30f;
    float l0 = 0.f,    l1 = 0.f;
    float o[8][4];
#pragma unroll
    for (int dt = 0; dt < 8; dt++)
#pragma unroll
        for (int i = 0; i < 4; i++) o[dt][i] = 0.f;

    for (int c = 0; c < NCHUNK; c++) {
        if (c < NCHUNK - 1) {
            int vs;
            const __half* vsrc = vsrc_of(c + 1, vs);
            load_tile(kbuf + ((c + 1) & 1) * KVH_TILE, ksrc_of(c + 1), HD);
            load_tile(vbuf + ((c + 1) & 1) * KVH_TILE, vsrc, vs);
            cp_commit();
            cp_wait<1>();
        } else {
            cp_wait<0>();
        }
        __syncthreads();

        const uint32_t Kb = kb_b + (c & 1) * KVH_TILE * 2;
        const uint32_t Vb = vb_b + (c & 1) * KVH_TILE * 2;

        // ---- S = Q K^T ----
        float cS[8][4];
#pragma unroll
        for (int nt = 0; nt < 8; nt++)
#pragma unroll
            for (int i = 0; i < 4; i++) cS[nt][i] = 0.f;

#pragma unroll
        for (int ks = 0; ks < 4; ks++) {
#pragma unroll
            for (int np = 0; np < 4; np++) {
                uint32_t b00, b01, b10, b11;
                const uint32_t addr = Kb
                    + (uint32_t)((np * 16 + b_radd) * KROWB + (ks * 16 + b_kadd) * 2);
                ldm_x4(b00, b01, b10, b11, addr);
                MMA_F16(cS[2 * np],     qa[ks], b00, b01);
                MMA_F16(cS[2 * np + 1], qa[ks], b10, b11);
            }
        }

        // ---- mask + scale + chunk row max ----
        float cm0 = -1e30f, cm1 = -1e30f;
#pragma unroll
        for (int nt = 0; nt < 8; nt++) {
            const int col = c * 64 + nt * 8 + 2 * lq;
            const float mv0 = mask_s[col];
            const float mv1 = mask_s[col + 1];
            cS[nt][0] = cS[nt][0] * 0.125f + mv0;
            cS[nt][1] = cS[nt][1] * 0.125f + mv1;
            cS[nt][2] = cS[nt][2] * 0.125f + mv0;
            cS[nt][3] = cS[nt][3] * 0.125f + mv1;
            cm0 = fmaxf(cm0, fmaxf(cS[nt][0], cS[nt][1]));
            cm1 = fmaxf(cm1, fmaxf(cS[nt][2], cS[nt][3]));
        }
#pragma unroll
        for (int off = 1; off <= 2; off <<= 1) {
            cm0 = fmaxf(cm0, __shfl_xor_sync(0xFFFFFFFFu, cm0, off));
            cm1 = fmaxf(cm1, __shfl_xor_sync(0xFFFFFFFFu, cm1, off));
        }

        const float mn0 = fmaxf(m0, cm0);
        const float mn1 = fmaxf(m1, cm1);
        const float a0  = __expf(m0 - mn0);
        const float a1  = __expf(m1 - mn1);
        m0 = mn0; m1 = mn1;

        float s0 = 0.f, s1 = 0.f;
#pragma unroll
        for (int nt = 0; nt < 8; nt++) {
            cS[nt][0] = __expf(cS[nt][0] - mn0);
            cS[nt][1] = __expf(cS[nt][1] - mn0);
            cS[nt][2] = __expf(cS[nt][2] - mn1);
            cS[nt][3] = __expf(cS[nt][3] - mn1);
            s0 += cS[nt][0] + cS[nt][1];
            s1 += cS[nt][2] + cS[nt][3];
        }
#pragma unroll
        for (int off = 1; off <= 2; off <<= 1) {
            s0 += __shfl_xor_sync(0xFFFFFFFFu, s0, off);
            s1 += __shfl_xor_sync(0xFFFFFFFFu, s1, off);
        }
        l0 = l0 * a0 + s0;
        l1 = l1 * a1 + s1;

#pragma unroll
        for (int dt = 0; dt < 8; dt++) {
            o[dt][0] *= a0; o[dt][1] *= a0;
            o[dt][2] *= a1; o[dt][3] *= a1;
        }

        // ---- PV: in-thread P pack, Vt via ldmatrix ----
#pragma unroll
        for (int kt = 0; kt < 4; kt++) {
            uint32_t pa[4];
            pa[0] = h2u(__floats2half2_rn(cS[2 * kt][0],     cS[2 * kt][1]));
            pa[1] = h2u(__floats2half2_rn(cS[2 * kt][2],     cS[2 * kt][3]));
            pa[2] = h2u(__floats2half2_rn(cS[2 * kt + 1][0], cS[2 * kt + 1][1]));
            pa[3] = h2u(__floats2half2_rn(cS[2 * kt + 1][2], cS[2 * kt + 1][3]));
#pragma unroll
            for (int np = 0; np < 4; np++) {
                uint32_t b00, b01, b10, b11;
                const uint32_t addr = Vb
                    + (uint32_t)((np * 16 + b_radd) * KROWB + (kt * 16 + b_kadd) * 2);
                ldm_x4(b00, b01, b10, b11, addr);
                MMA_F16(o[2 * np],     pa, b00, b01);
                MMA_F16(o[2 * np + 1], pa, b10, b11);
            }
        }
        __syncthreads();
    }

    // epilogue: normalize + write out[b, s, h*64 + d]
    {
        const float r0 = 1.f / l0;
        const float r1 = 1.f / l1;
        const int r = w * 16 + lr;
        float* ob0 = outctx + ((size_t)b * NS + r) * NHID + h * HD;
        float* ob1 = outctx + ((size_t)b * NS + r + 8) * NHID + h * HD;
#pragma unroll
        for (int dt = 0; dt < 8; dt++) {
            const int dcol = dt * 8 + 2 * lq;
            float2 v0, v1;
            v0.x = o[dt][0] * r0; v0.y = o[dt][1] * r0;
            v1.x = o[dt][2] * r1; v1.y = o[dt][3] * r1;
            *(float2*)&ob0[dcol] = v0;
            *(float2*)&ob1[dcol] = v1;
        }
    }
}

// =====================================================================
// Host launcher
// =====================================================================
extern "C" void kernel_launch(void* const* d_in, const int* in_sizes, int n_in,
                              void* d_out, int out_size)
{
    const float* hidden = (const float*)d_in[0];
    const float* mask   = (const float*)d_in[1];
    const float* Wq     = (const float*)d_in[2];
    const float* bq     = (const float*)d_in[3];
    const float* Wk     = (const float*)d_in[4];
    const float* bk     = (const float*)d_in[5];
    const float* Wv     = (const float*)d_in[6];
    const float* bv     = (const float*)d_in[7];
    const float* c0k    = (const float*)d_in[8];
    const float* c0v    = (const float*)d_in[9];
    const float* c1k    = (const float*)d_in[10];
    const float* c1v    = (const float*)d_in[11];

    float* out   = (float*)d_out;
    const size_t sect = (size_t)NB * NS * NHID;
    float* out_k = out + sect;
    float* out_v = out + 2 * sect;

    __half *hidh_d, *wh_d, *c0kh_d, *c0vt_d, *c1kh_d, *c1vt_d;
    cudaGetSymbolAddress((void**)&hidh_d, g_hidh);
    cudaGetSymbolAddress((void**)&wh_d,   g_wh);
    cudaGetSymbolAddress((void**)&c0kh_d, g_c0kh);
    cudaGetSymbolAddress((void**)&c0vt_d, g_c0vt);
    cudaGetSymbolAddress((void**)&c1kh_d, g_c1kh);
    cudaGetSymbolAddress((void**)&c1vt_d, g_c1vt);

    const int gemm_smem = 2 * STAGEW * 4;                 // 30720
    const int attn_smem = 4 * KVH_TILE * 2 + LTOT * 4;    // 39168

    cudaFuncSetAttribute(qkv_gemm_f16,
                         cudaFuncAttributeMaxDynamicSharedMemorySize, gemm_smem);
    cudaFuncSetAttribute(attn_flash_f16,
                         cudaFuncAttributeMaxDynamicSharedMemorySize, attn_smem);

    // preprocessing: fp16 converts + V transposes
    const int nh4  = (NB * NS * NHID) / 4;
    const int nw4  = (NHID * NHID) / 4;
    const int nc04 = (8 * NH * L0 * HD) / 4;
    const int nc14 = (NB * NH * L1 * HD) / 4;
    cvt_f16_kernel<<<2048, 256>>>((const float4*)hidden, (uint2*)hidh_d, nh4);
    cvt_f16_kernel<<<288, 256>>>((const float4*)Wq, (uint2*)(wh_d), nw4);
    cvt_f16_kernel<<<288, 256>>>((const float4*)Wk, (uint2*)(wh_d + (size_t)NHID * NHID), nw4);
    cvt_f16_kernel<<<288, 256>>>((const float4*)Wv, (uint2*)(wh_d + (size_t)2 * NHID * NHID), nw4);
    cvt_f16_kernel<<<1024, 256>>>((const float4*)c0k, (uint2*)c0kh_d, nc04);
    cvt_f16_kernel<<<4096, 256>>>((const float4*)c1k, (uint2*)c1kh_d, nc14);
    {
        dim3 g0(L0 / 64, 8 * NH);
        transpose_f16_kernel<<<g0, 256>>>(c0v, c0vt_d, L0);
        dim3 g1(L1 / 64, NB * NH);
        transpose_f16_kernel<<<g1, 256>>>(c1v, c1vt_d, L1);
    }

    dim3 ggrid(NB * NS / 128, 3 * NHID / 64);       // (120, 36)
    qkv_gemm_f16<<<ggrid, 256, gemm_smem>>>(bq, bk, bv, out_k, out_v);

    attn_flash_f16<<<NB * NH, 128, attn_smem>>>(mask, out);
}

// round 11
// speedup vs baseline: 2.1694x; 1.2196x over previous
#include <cuda_runtime.h>
#include <cuda_fp16.h>
#include <cstdint>

// ---------------- problem constants (fixed by the dataset) ----------------
#define NB    240
#define NS    64
#define NHID  768
#define NH    12
#define HD    64
#define L0    384
#define L1    128
#define LTOT  576
#define NCHUNK 9

// device-global scratch (allocation-free)
__device__ __half g_hidh[(size_t)NB * NS * NHID];       // hidden fp16
__device__ __half g_wh  [(size_t)3 * NHID * NHID];      // Wq|Wk|Wv fp16
__device__ __half g_qh  [(size_t)NB * NH * NS * HD];    // q fp16 [bh][s][d]
__device__ __half g_kh  [(size_t)NB * NH * NS * HD];    // k fp16 [bh][s][d]
__device__ __half g_vth [(size_t)NB * NH * NS * HD];    // v fp16 T [bh][d][s]
__device__ __half g_c0kh[(size_t)8 * NH * L0 * HD];     // c0 key fp16 [g][j][d]
__device__ __half g_c0vt[(size_t)8 * NH * L0 * HD];     // c0 val fp16 T [g][d][j]
__device__ __half g_c1kh[(size_t)NB * NH * L1 * HD];    // c1 key fp16
__device__ __half g_c1vt[(size_t)NB * NH * L1 * HD];    // c1 val fp16 T

// ---------------- helpers ----------------
__device__ __forceinline__ uint32_t h2u(__half2 h) { return *(uint32_t*)&h; }

__device__ __forceinline__ uint32_t smem_u32(const void* p) {
    uint32_t a;
    asm("{ .reg .u64 t; cvta.to.shared.u64 t, %1; cvt.u32.u64 %0, t; }"
        : "=r"(a) : "l"(p));
    return a;
}

#define MMA_F16(c, a, b0, b1)                                               \
    asm volatile(                                                           \
        "mma.sync.aligned.m16n8k16.row.col.f32.f16.f16.f32 "                \
        "{%0,%1,%2,%3}, {%4,%5,%6,%7}, {%8,%9}, {%0,%1,%2,%3};\n"           \
        : "+f"((c)[0]), "+f"((c)[1]), "+f"((c)[2]), "+f"((c)[3])            \
        : "r"((a)[0]), "r"((a)[1]), "r"((a)[2]), "r"((a)[3]),               \
          "r"(b0), "r"(b1))

__device__ __forceinline__ void ldm_x4(uint32_t& r0, uint32_t& r1,
                                       uint32_t& r2, uint32_t& r3,
                                       uint32_t addr) {
    asm volatile("ldmatrix.sync.aligned.m8n8.x4.shared.b16 {%0,%1,%2,%3}, [%4];"
                 : "=r"(r0), "=r"(r1), "=r"(r2), "=r"(r3) : "r"(addr));
}

__device__ __forceinline__ void cp16h(__half* dst, const __half* src) {
    uint32_t d = (uint32_t)__cvta_generic_to_shared(dst);
    asm volatile("cp.async.cg.shared.global [%0], [%1], 16;\n" :: "r"(d), "l"(src));
}
__device__ __forceinline__ void cp16f(float* dst, const float* src) {
    uint32_t d = (uint32_t)__cvta_generic_to_shared(dst);
    asm volatile("cp.async.cg.shared.global [%0], [%1], 16;\n" :: "r"(d), "l"(src));
}
__device__ __forceinline__ void cp_commit() {
    asm volatile("cp.async.commit_group;\n");
}
template <int N> __device__ __forceinline__ void cp_wait() {
    asm volatile("cp.async.wait_group %0;\n" :: "n"(N));
}

// =====================================================================
// Fused float->fp16 conversion over ALL segments (one launch).
// Segments (float4 units): hidden 2949120 | Wq 147456 | Wk | Wv |
//                          c0k 589824 | c1k 5898240.  Total 9879552.
// =====================================================================
#define SEG0 2949120
#define SEG1 (SEG0 + 147456)
#define SEG2 (SEG1 + 147456)
#define SEG3 (SEG2 + 147456)
#define SEG4 (SEG3 + 589824)
#define SEG5 (SEG4 + 5898240)

__global__ __launch_bounds__(256) void cvt_all_kernel(
    const float4* __restrict__ hid, const float4* __restrict__ wq,
    const float4* __restrict__ wk,  const float4* __restrict__ wv,
    const float4* __restrict__ c0k, const float4* __restrict__ c1k,
    uint2* __restrict__ d_hid, uint2* __restrict__ d_w,
    uint2* __restrict__ d_c0k, uint2* __restrict__ d_c1k)
{
    const int stride = gridDim.x * blockDim.x;
    for (int i = blockIdx.x * blockDim.x + threadIdx.x; i < SEG5; i += stride) {
        const float4* s;
        uint2* d;
        if (i < SEG0)      { s = hid + i;          d = d_hid + i; }
        else if (i < SEG1) { s = wq + (i - SEG0);  d = d_w + (i - SEG0); }
        else if (i < SEG2) { s = wk + (i - SEG1);  d = d_w + 147456 + (i - SEG1); }
        else if (i < SEG3) { s = wv + (i - SEG2);  d = d_w + 2 * 147456 + (i - SEG2); }
        else if (i < SEG4) { s = c0k + (i - SEG3); d = d_c0k + (i - SEG3); }
        else               { s = c1k + (i - SEG4); d = d_c1k + (i - SEG4); }
        float4 v = *s;
        __half2 lo = __floats2half2_rn(v.x, v.y);
        __half2 hi = __floats2half2_rn(v.z, v.w);
        uint2 o;
        o.x = h2u(lo);
        o.y = h2u(hi);
        *d = o;
    }
}

// =====================================================================
// Fused V transpose: fp32 [G][R][64] -> fp16 [G][64][R], c0v + c1v in
// one launch (block-range dispatch).
// =====================================================================
#define NT0 (8 * NH * (L0 / 64))     // 576 c0 tiles
#define NT1 (NB * NH * (L1 / 64))    // 5760 c1 tiles

__global__ __launch_bounds__(256) void transpose_all_kernel(
    const float* __restrict__ c0v, const float* __restrict__ c1v,
    __half* __restrict__ d_c0, __half* __restrict__ d_c1)
{
    __shared__ float t[64][65];
    const int tid = threadIdx.x;

    const float* src;
    __half* dst;
    int g, r0, R;
    if (blockIdx.x < NT0) {
        g = blockIdx.x / (L0 / 64); r0 = (blockIdx.x % (L0 / 64)) * 64;
        R = L0; src = c0v; dst = d_c0;
    } else {
        const int i = blockIdx.x - NT0;
        g = i / (L1 / 64); r0 = (i % (L1 / 64)) * 64;
        R = L1; src = c1v; dst = d_c1;
    }

    const float* s = src + ((size_t)g * R + r0) * 64;
    for (int i = tid; i < 4096; i += 256) {
        const int r = i >> 6, d = i & 63;
        t[r][d] = s[r * 64 + d];
    }
    __syncthreads();
    __half* o = dst + (size_t)g * 64 * R + r0;
    for (int i = tid; i < 4096; i += 256) {
        const int d = i >> 6, r = i & 63;
        o[(size_t)d * R + r] = __float2half(t[r][d]);
    }
}

// =====================================================================
// QKV projection, fp16 mma + ldmatrix, 3-stage cp.async pipeline.
// Block 128x64, BK=32, 8 warps (4x2), warp tile 32x32; 15 KB stages.
// =====================================================================
#define GLDW  20
#define A_W   (128 * GLDW)
#define B_W   (64 * GLDW)
#define STAGEW (A_W + B_W)
#define ROWB  80

__global__ __launch_bounds__(256, 3) void qkv_gemm_f16(
    const float* __restrict__ bq, const float* __restrict__ bk_,
    const float* __restrict__ bv,
    float* __restrict__ out_k, float* __restrict__ out_v)
{
    extern __shared__ uint32_t smw[];
    const uint32_t smem_b = smem_u32(smw);

    const int m0  = blockIdx.x * 128;
    const int n0g = blockIdx.y * 64;
    const int mat = n0g / NHID;
    const int n0  = n0g - mat * NHID;

    const __half* Ag = g_hidh;
    const __half* Bg = g_wh + (size_t)mat * NHID * NHID;
    const float*  bi = (mat == 0) ? bq : (mat == 1) ? bk_ : bv;

    const int tid  = threadIdx.x;
    const int lane = tid & 31;
    const int w    = tid >> 5;
    const int wm   = w & 3;
    const int wn   = w >> 2;
    const int lq   = lane & 3;
    const int lr   = lane >> 2;

    // ldmatrix per-lane addressing
    const int lg = lane >> 3, lrs = lane & 7;
    const int a_radd = (lg & 1) * 8 + lrs;
    const int a_kadd = (lg >> 1) * 8;
    const int b_radd = (lg >> 1) * 8 + lrs;
    const int b_kadd = (lg & 1) * 8;

    // cp.async staging mapping
    const int arow = tid >> 2;          // 0..63
    const int acu  = tid & 3;           // 16B unit (8 halves)

    auto load_stage = [&](int s, int k0) {
        __half* A = (__half*)smw + s * STAGEW * 2;
        __half* B = A + A_W * 2;
        cp16h(A + arow * 40 + acu * 8,
              Ag + (size_t)(m0 + arow) * NHID + k0 + acu * 8);
        cp16h(A + (arow + 64) * 40 + acu * 8,
              Ag + (size_t)(m0 + arow + 64) * NHID + k0 + acu * 8);
        cp16h(B + arow * 40 + acu * 8,
              Bg + (size_t)(n0 + arow) * NHID + k0 + acu * 8);
    };

    float acc[2][4][4];
#pragma unroll
    for (int mt = 0; mt < 2; mt++)
#pragma unroll
        for (int nt = 0; nt < 4; nt++)
#pragma unroll
            for (int i = 0; i < 4; i++) acc[mt][nt][i] = 0.f;

    auto compute = [&](int s) {
        const uint32_t Ab = smem_b + s * STAGEW * 4;
        const uint32_t Bb = Ab + A_W * 4;
#pragma unroll
        for (int ks = 0; ks < 2; ks++) {
            uint32_t af[2][4];
#pragma unroll
            for (int mt = 0; mt < 2; mt++) {
                const uint32_t addr = Ab
                    + (uint32_t)((wm * 32 + mt * 16 + a_radd) * ROWB
                                 + (ks * 16 + a_kadd) * 2);
                ldm_x4(af[mt][0], af[mt][1], af[mt][2], af[mt][3], addr);
            }
            uint32_t bf[4][2];
#pragma unroll
            for (int np = 0; np < 2; np++) {
                const uint32_t addr = Bb
                    + (uint32_t)((wn * 32 + np * 16 + b_radd) * ROWB
                                 + (ks * 16 + b_kadd) * 2);
                ldm_x4(bf[2 * np][0], bf[2 * np][1],
                       bf[2 * np + 1][0], bf[2 * np + 1][1], addr);
            }
#pragma unroll
            for (int mt = 0; mt < 2; mt++)
#pragma unroll
                for (int nt = 0; nt < 4; nt++)
                    MMA_F16(acc[mt][nt], af[mt], bf[nt][0], bf[nt][1]);
        }
    };

    // 3-stage pipeline: 2 in flight; issue it+2 while computing it.
    load_stage(0, 0);  cp_commit();
    load_stage(1, 32); cp_commit();

    for (int it = 0; it < 24; it++) {
        if (it < 23) cp_wait<1>(); else cp_wait<0>();
        __syncthreads();
        if (it + 2 < 24) {
            load_stage((it + 2) % 3, (it + 2) * 32);
            cp_commit();
        }
        compute(it % 3);
    }

    // epilogue: bias + scatter (fp32 k/v outputs + fp16 q/k + fp16 v^T)
#pragma unroll
    for (int nt = 0; nt < 4; nt++) {
        const int ncol = n0 + wn * 32 + nt * 8 + 2 * lq;
        const float b0 = bi[ncol];
        const float b1 = bi[ncol + 1];
        const int h = ncol >> 6;
        const int d = ncol & 63;
#pragma unroll
        for (int mt = 0; mt < 2; mt++) {
            const int r = wm * 32 + mt * 16 + lr;
#pragma unroll
            for (int half = 0; half < 2; half++) {
                const int m = m0 + r + 8 * half;
                const int b = m >> 6;
                const int s = m & 63;
                const size_t bh = (size_t)b * NH + h;
                float2 v;
                v.x = acc[mt][nt][2 * half + 0] + b0;
                v.y = acc[mt][nt][2 * half + 1] + b1;
                if (mat == 0) {
                    *(__half2*)&g_qh[(bh * 64 + s) * 64 + d] =
                        __floats2half2_rn(v.x, v.y);
                } else if (mat == 1) {
                    *(float2*)&out_k[(bh * 64 + s) * 64 + d] = v;
                    *(__half2*)&g_kh[(bh * 64 + s) * 64 + d] =
                        __floats2half2_rn(v.x, v.y);
                } else {
                    *(float2*)&out_v[(bh * 64 + s) * 64 + d] = v;
                    g_vth[(bh * 64 + d) * 64 + s]     = __float2half(v.x);
                    g_vth[(bh * 64 + d + 1) * 64 + s] = __float2half(v.y);
                }
            }
        }
    }
}

// =====================================================================
// Flash cache attention, fp16 mma + ldmatrix (round-10 proven), with
// occupancy bumped to 4 blocks/SM.
// =====================================================================
#define KVH_LD 72
#define KVH_TILE (64 * KVH_LD)
#define KROWB 144

__global__ __launch_bounds__(128, 4) void attn_flash_f16(
    const float* __restrict__ mask,
    float* __restrict__ outctx)
{
    extern __shared__ __half smh[];
    __half* kbuf   = smh;                       // [2][64][72]
    __half* vbuf   = kbuf + 2 * KVH_TILE;       // [2][64][72]
    float*  mask_s = (float*)(vbuf + 2 * KVH_TILE);   // [576]
    const uint32_t kb_b = smem_u32(kbuf);
    const uint32_t vb_b = smem_u32(vbuf);

    const int bh   = blockIdx.x;
    const int b    = bh / NH;
    const int h    = bh - b * NH;
    const int tid  = threadIdx.x;
    const int lane = tid & 31;
    const int w    = tid >> 5;
    const int lq   = lane & 3;
    const int lr   = lane >> 2;

    const int lg = lane >> 3, lrs = lane & 7;
    const int b_radd = (lg >> 1) * 8 + lrs;
    const int b_kadd = (lg & 1) * 8;

    const __half* c0kb = g_c0kh + ((size_t)(b & 7) * NH + h) * L0 * HD;
    const __half* c0vb = g_c0vt + ((size_t)(b & 7) * NH + h) * HD * L0;
    const __half* c1kb = g_c1kh + (size_t)bh * L1 * HD;
    const __half* c1vb = g_c1vt + (size_t)bh * HD * L1;
    const __half* ksb  = g_kh  + (size_t)bh * NS * HD;
    const __half* vsb  = g_vth + (size_t)bh * HD * NS;

    auto ksrc_of = [&](int c) -> const __half* {
        return (c < 6) ? (c0kb + c * 64 * HD)
             : (c < 8) ? (c1kb + (c - 6) * 64 * HD) : ksb;
    };
    auto vsrc_of = [&](int c, int& vstride) -> const __half* {
        if (c < 6)  { vstride = L0; return c0vb + c * 64; }
        if (c < 8)  { vstride = L1; return c1vb + (c - 6) * 64; }
        vstride = NS; return vsb;
    };

    auto load_tile = [&](__half* buf, const __half* src, int sstride) {
        const int r  = tid >> 1;
        const int c0 = (tid & 1) * 32;
        __half* d = buf + r * KVH_LD + c0;
        const __half* s = src + (size_t)r * sstride + c0;
#pragma unroll
        for (int i = 0; i < 4; i++) cp16h(d + 8 * i, s + 8 * i);
    };

    // prologue: Q -> kbuf[1]; chunk0 -> buf0; mask
    load_tile(kbuf + KVH_TILE, g_qh + (size_t)bh * NS * HD, HD);
    cp_commit();
    {
        int vs;
        const __half* vsrc = vsrc_of(0, vs);
        load_tile(kbuf, ksrc_of(0), HD);
        load_tile(vbuf, vsrc, vs);
        cp_commit();
    }
    for (int i = tid * 4; i < LTOT; i += 128 * 4)
        cp16f(mask_s + i, mask + (size_t)b * LTOT + i);
    cp_commit();

    cp_wait<2>();
    __syncthreads();

    // Q fragments via ldmatrix (A-operand shape)
    uint32_t qa[4][4];
    {
        const int a_radd = (lg & 1) * 8 + lrs;
        const int a_kadd = (lg >> 1) * 8;
        const uint32_t Qb = kb_b + KVH_TILE * 2;
#pragma unroll
        for (int ks = 0; ks < 4; ks++) {
            const uint32_t addr = Qb
                + (uint32_t)((w * 16 + a_radd) * KROWB + (ks * 16 + a_kadd) * 2);
            ldm_x4(qa[ks][0], qa[ks][1], qa[ks][2], qa[ks][3], addr);
        }
    }
    __syncthreads();

    float m0 = -1e30f, m1 = -1e30f;
    float l0 = 0.f,    l1 = 0.f;
    float o[8][4];
#pragma unroll
    for (int dt = 0; dt < 8; dt++)
#pragma unroll
        for (int i = 0; i < 4; i++) o[dt][i] = 0.f;

    for (int c = 0; c < NCHUNK; c++) {
        if (c < NCHUNK - 1) {
            int vs;
            const __half* vsrc = vsrc_of(c + 1, vs);
            load_tile(kbuf + ((c + 1) & 1) * KVH_TILE, ksrc_of(c + 1), HD);
            load_tile(vbuf + ((c + 1) & 1) * KVH_TILE, vsrc, vs);
            cp_commit();
            cp_wait<1>();
        } else {
            cp_wait<0>();
        }
        __syncthreads();

        const uint32_t Kb = kb_b + (c & 1) * KVH_TILE * 2;
        const uint32_t Vb = vb_b + (c & 1) * KVH_TILE * 2;

        // ---- S = Q K^T ----
        float cS[8][4];
#pragma unroll
        for (int nt = 0; nt < 8; nt++)
#pragma unroll
            for (int i = 0; i < 4; i++) cS[nt][i] = 0.f;

#pragma unroll
        for (int ks = 0; ks < 4; ks++) {
#pragma unroll
            for (int np = 0; np < 4; np++) {
                uint32_t b00, b01, b10, b11;
                const uint32_t addr = Kb
                    + (uint32_t)((np * 16 + b_radd) * KROWB + (ks * 16 + b_kadd) * 2);
                ldm_x4(b00, b01, b10, b11, addr);
                MMA_F16(cS[2 * np],     qa[ks], b00, b01);
                MMA_F16(cS[2 * np + 1], qa[ks], b10, b11);
            }
        }

        // ---- mask + scale + chunk row max ----
        float cm0 = -1e30f, cm1 = -1e30f;
#pragma unroll
        for (int nt = 0; nt < 8; nt++) {
            const int col = c * 64 + nt * 8 + 2 * lq;
            const float mv0 = mask_s[col];
            const float mv1 = mask_s[col + 1];
            cS[nt][0] = cS[nt][0] * 0.125f + mv0;
            cS[nt][1] = cS[nt][1] * 0.125f + mv1;
            cS[nt][2] = cS[nt][2] * 0.125f + mv0;
            cS[nt][3] = cS[nt][3] * 0.125f + mv1;
            cm0 = fmaxf(cm0, fmaxf(cS[nt][0], cS[nt][1]));
            cm1 = fmaxf(cm1, fmaxf(cS[nt][2], cS[nt][3]));
        }
#pragma unroll
        for (int off = 1; off <= 2; off <<= 1) {
            cm0 = fmaxf(cm0, __shfl_xor_sync(0xFFFFFFFFu, cm0, off));
            cm1 = fmaxf(cm1, __shfl_xor_sync(0xFFFFFFFFu, cm1, off));
        }

        const float mn0 = fmaxf(m0, cm0);
        const float mn1 = fmaxf(m1, cm1);
        const float a0  = __expf(m0 - mn0);
        const float a1  = __expf(m1 - mn1);
        m0 = mn0; m1 = mn1;

        float s0 = 0.f, s1 = 0.f;
#pragma unroll
        for (int nt = 0; nt < 8; nt++) {
            cS[nt][0] = __expf(cS[nt][0] - mn0);
            cS[nt][1] = __expf(cS[nt][1] - mn0);
            cS[nt][2] = __expf(cS[nt][2] - mn1);
            cS[nt][3] = __expf(cS[nt][3] - mn1);
            s0 += cS[nt][0] + cS[nt][1];
            s1 += cS[nt][2] + cS[nt][3];
        }
#pragma unroll
        for (int off = 1; off <= 2; off <<= 1) {
            s0 += __shfl_xor_sync(0xFFFFFFFFu, s0, off);
            s1 += __shfl_xor_sync(0xFFFFFFFFu, s1, off);
        }
        l0 = l0 * a0 + s0;
        l1 = l1 * a1 + s1;

#pragma unroll
        for (int dt = 0; dt < 8; dt++) {
            o[dt][0] *= a0; o[dt][1] *= a0;
            o[dt][2] *= a1; o[dt][3] *= a1;
        }

        // ---- PV: in-thread P pack, Vt via ldmatrix ----
#pragma unroll
        for (int kt = 0; kt < 4; kt++) {
            uint32_t pa[4];
            pa[0] = h2u(__floats2half2_rn(cS[2 * kt][0],     cS[2 * kt][1]));
            pa[1] = h2u(__floats2half2_rn(cS[2 * kt][2],     cS[2 * kt][3]));
            pa[2] = h2u(__floats2half2_rn(cS[2 * kt + 1][0], cS[2 * kt + 1][1]));
            pa[3] = h2u(__floats2half2_rn(cS[2 * kt + 1][2], cS[2 * kt + 1][3]));
#pragma unroll
            for (int np = 0; np < 4; np++) {
                uint32_t b00, b01, b10, b11;
                const uint32_t addr = Vb
                    + (uint32_t)((np * 16 + b_radd) * KROWB + (kt * 16 + b_kadd) * 2);
                ldm_x4(b00, b01, b10, b11, addr);
                MMA_F16(o[2 * np],     pa, b00, b01);
                MMA_F16(o[2 * np + 1], pa, b10, b11);
            }
        }
        __syncthreads();
    }

    // epilogue: normalize + write out[b, s, h*64 + d]
    {
        const float r0 = 1.f / l0;
        const float r1 = 1.f / l1;
        const int r = w * 16 + lr;
        float* ob0 = outctx + ((size_t)b * NS + r) * NHID + h * HD;
        float* ob1 = outctx + ((size_t)b * NS + r + 8) * NHID + h * HD;
#pragma unroll
        for (int dt = 0; dt < 8; dt++) {
            const int dcol = dt * 8 + 2 * lq;
            float2 v0, v1;
            v0.x = o[dt][0] * r0; v0.y = o[dt][1] * r0;
            v1.x = o[dt][2] * r1; v1.y = o[dt][3] * r1;
            *(float2*)&ob0[dcol] = v0;
            *(float2*)&ob1[dcol] = v1;
        }
    }
}

// =====================================================================
// Host launcher
// =====================================================================
extern "C" void kernel_launch(void* const* d_in, const int* in_sizes, int n_in,
                              void* d_out, int out_size)
{
    const float* hidden = (const float*)d_in[0];
    const float* mask   = (const float*)d_in[1];
    const float* Wq     = (const float*)d_in[2];
    const float* bq     = (const float*)d_in[3];
    const float* Wk     = (const float*)d_in[4];
    const float* bk     = (const float*)d_in[5];
    const float* Wv     = (const float*)d_in[6];
    const float* bv     = (const float*)d_in[7];
    const float* c0k    = (const float*)d_in[8];
    const float* c0v    = (const float*)d_in[9];
    const float* c1k    = (const float*)d_in[10];
    const float* c1v    = (const float*)d_in[11];

    float* out   = (float*)d_out;
    const size_t sect = (size_t)NB * NS * NHID;
    float* out_k = out + sect;
    float* out_v = out + 2 * sect;

    __half *hidh_d, *wh_d, *c0kh_d, *c0vt_d, *c1kh_d, *c1vt_d;
    cudaGetSymbolAddress((void**)&hidh_d, g_hidh);
    cudaGetSymbolAddress((void**)&wh_d,   g_wh);
    cudaGetSymbolAddress((void**)&c0kh_d, g_c0kh);
    cudaGetSymbolAddress((void**)&c0vt_d, g_c0vt);
    cudaGetSymbolAddress((void**)&c1kh_d, g_c1kh);
    cudaGetSymbolAddress((void**)&c1vt_d, g_c1vt);

    const int gemm_smem = 3 * STAGEW * 4;                 // 46080
    const int attn_smem = 4 * KVH_TILE * 2 + LTOT * 4;    // 39168

    cudaFuncSetAttribute(qkv_gemm_f16,
                         cudaFuncAttributeMaxDynamicSharedMemorySize, gemm_smem);
    cudaFuncSetAttribute(attn_flash_f16,
                         cudaFuncAttributeMaxDynamicSharedMemorySize, attn_smem);

    // preprocessing: 2 fused launches
    cvt_all_kernel<<<4096, 256>>>(
        (const float4*)hidden, (const float4*)Wq, (const float4*)Wk,
        (const float4*)Wv, (const float4*)c0k, (const float4*)c1k,
        (uint2*)hidh_d, (uint2*)wh_d, (uint2*)c0kh_d, (uint2*)c1kh_d);
    transpose_all_kernel<<<NT0 + NT1, 256>>>(c0v, c1v, c0vt_d, c1vt_d);

    dim3 ggrid(NB * NS / 128, 3 * NHID / 64);       // (120, 36)
    qkv_gemm_f16<<<ggrid, 256, gemm_smem>>>(bq, bk, bv, out_k, out_v);

    attn_flash_f16<<<NB * NH, 128, attn_smem>>>(mask, out);
}